// round 13
// baseline (speedup 1.0000x reference)
#include <cuda_runtime.h>
#include <cuda_fp16.h>
#include <math.h>

// Problem constants (match reference)
#define NN 50000
#define NE 800000
#define IN_F 256
#define D1 128      // HEADS*HID
#define OUT_F 64
#define SLOPE 0.2f

#define SCAN_B 1024
#define NBLK ((NN + SCAN_B - 1) / SCAN_B)   // 49

// ---------------- device scratch (no allocations allowed) ----------------
__device__ __align__(16) __half g_h[(size_t)NN * D1];    // GEMM output, fp16 (gather path)
__device__ __align__(16) float  g_act[(size_t)NN * D1];  // post-aggregate activations, fp32
__device__ __align__(16) float  g_als[(size_t)NN * 4];
__device__ __align__(16) float  g_ald[(size_t)NN * 4];
__device__ int   g_rowptr[NN + 1];
__device__ int   g_deg[NN];
__device__ int   g_cursor[NN];
__device__ __align__(8) int2 g_csr[NE];    // (src, weight-bits) packed
__device__ int   g_bsum[NBLK];
__device__ int   g_boff[NBLK];
__device__ unsigned g_mxals[3][4];         // per-layer per-head global max(als), int-encoded
__device__ int   g_idx64;

// monotone float<->uint encoding for atomicMax on floats (0u acts as -inf)
__device__ __forceinline__ unsigned fenc(float f) {
    int b = __float_as_int(f);
    return (b >= 0) ? ((unsigned)b | 0x80000000u) : ~(unsigned)b;
}
__device__ __forceinline__ float fdec(unsigned u) {
    int b = (u & 0x80000000u) ? (int)(u & 0x7fffffffu) : ~(int)u;
    return __int_as_float(b);
}

// ---------------- fused: zero deg + dtype detect (block 0) ----------------
__global__ void k_detect_zero(const void* ei_raw, int E, int n) {
    int i = blockIdx.x * blockDim.x + threadIdx.x;
    if (i < n) g_deg[i] = 0;
    if (blockIdx.x == 0) {
        __shared__ int ok;
        if (threadIdx.x == 0) ok = 1;
        __syncthreads();
        const long long* p = (const long long*)ei_raw;
        int nchk = 2 * E < 256 ? 2 * E : 256;
        if (threadIdx.x < nchk) {
            long long v = p[threadIdx.x];
            if (v < 0 || v >= NN) atomicAnd(&ok, 0);
        }
        __syncthreads();
        if (threadIdx.x == 0) g_idx64 = ok;
    }
}

__device__ __forceinline__ void load_edge(const void* ei_raw, int E, int e, int idx64,
                                          int& s, int& d) {
    if (idx64) {
        const long long* p = (const long long*)ei_raw;
        s = (int)p[e];
        d = (int)p[E + e];
    } else {
        const int* p = (const int*)ei_raw;
        s = p[e];
        d = p[E + e];
    }
}

// ---------------- CSR construction ----------------
__global__ void k_count_deg(const void* ei_raw, int E, int n) {
    int e = blockIdx.x * blockDim.x + threadIdx.x;
    int idx64 = g_idx64;
    if (e < E) {
        int s, d;
        load_edge(ei_raw, E, e, idx64, s, d);
        if (d >= 0 && d < n) atomicAdd(&g_deg[d], 1);
    }
}

__global__ void k_scan1(int n) {
    int t = threadIdx.x;
    int i = blockIdx.x * SCAN_B + t;
    int lane = t & 31, w = t >> 5;
    int v = (i < n) ? g_deg[i] : 0;
    int x = v;
#pragma unroll
    for (int o = 1; o < 32; o <<= 1) {
        int y = __shfl_up_sync(0xffffffffu, x, o);
        if (lane >= o) x += y;
    }
    __shared__ int ws[32];
    if (lane == 31) ws[w] = x;
    __syncthreads();
    if (w == 0) {
        int y = ws[lane];
#pragma unroll
        for (int o = 1; o < 32; o <<= 1) {
            int z = __shfl_up_sync(0xffffffffu, y, o);
            if (lane >= o) y += z;
        }
        ws[lane] = y;
    }
    __syncthreads();
    int incl = x + (w > 0 ? ws[w - 1] : 0);
    if (i < n) g_rowptr[i + 1] = incl;
    if (t == SCAN_B - 1) g_bsum[blockIdx.x] = incl;
}

__global__ void k_scan2() {
    int t = threadIdx.x;
    int lane = t & 31, w = t >> 5;
    if (t < 12) ((unsigned*)g_mxals)[t] = 0u;    // init per-layer max slots
    int v = (t < NBLK) ? g_bsum[t] : 0;
    int x = v;
#pragma unroll
    for (int o = 1; o < 32; o <<= 1) {
        int y = __shfl_up_sync(0xffffffffu, x, o);
        if (lane >= o) x += y;
    }
    __shared__ int ws[2];
    if (lane == 31) ws[w] = x;
    __syncthreads();
    int incl = x + (w > 0 ? ws[0] : 0);
    if (t < NBLK) g_boff[t] = incl - v;
}

__global__ void k_scan3(int n) {
    int i = blockIdx.x * blockDim.x + threadIdx.x;
    if (i < n) {
        int incl = g_rowptr[i + 1] + g_boff[i >> 10];
        g_rowptr[i + 1] = incl;
        g_cursor[i] = incl - g_deg[i];
        if (i == 0) g_rowptr[0] = 0;
    }
}

__global__ void k_scatter(const void* ei_raw, const float* __restrict__ ew, int E, int n) {
    int e = blockIdx.x * blockDim.x + threadIdx.x;
    int idx64 = g_idx64;
    if (e < E) {
        int s, d;
        load_edge(ei_raw, E, e, idx64, s, d);
        if (s >= 0 && s < n && d >= 0 && d < n) {
            int pos = atomicAdd(&g_cursor[d], 1);
            if (pos >= 0 && pos < E) {
                g_csr[pos] = make_int2(s, __float_as_int(ew[e]));
            }
        }
    }
}

// ---------------- FP16 tensor-core GEMM (m16n8k16, fp32 accum) ----------------
// g_h[M,Nc] (fp16) = A[M,K] @ B[K,Nc]. BM=128, BN=64, BK=32, 8 warps, warp tile 32x32.
// fp16 mantissa == tf32 mantissa (10 bits) => same rounding error as tf32 path.
// Pitch 40 halves (80B) => 20-bank shift/row => fragment reads conflict-free.
__global__ __launch_bounds__(256)
void k_gemm_f16(const float* __restrict__ Aext, const float* __restrict__ B,
                int M, int K, int Nc) {
    constexpr int BM = 128, BN = 64, BK = 32;
    constexpr int AP = 40;   // As row pitch (halves)
    constexpr int BP = 40;   // Bs row pitch (halves)
    __shared__ __align__(16) __half As[BM][AP];   // [m][k]
    __shared__ __align__(16) __half Bs[BN][BP];   // [n][k]  (transposed at load)

    const float* __restrict__ A = Aext ? Aext : g_act;
    __half* __restrict__ C = g_h;

    int tid = threadIdx.x;
    int lane = tid & 31;
    int warp = tid >> 5;
    int wm = warp >> 1;
    int wn = warp & 1;
    int bm0 = blockIdx.y * BM;
    int bn0 = blockIdx.x * BN;

    float acc[2][4][4];
#pragma unroll
    for (int mt = 0; mt < 2; mt++)
#pragma unroll
        for (int nt = 0; nt < 4; nt++)
#pragma unroll
            for (int i = 0; i < 4; i++) acc[mt][nt][i] = 0.f;

    // A loader: 2 threads/row, 16 floats each -> 16 halves (2x uint4 STS)
    int arow = tid >> 1;
    int acol0 = (tid & 1) * 16;
    int grow = bm0 + arow;
    // B loader: thread t handles row k=t>>3 (0..31), 8 n at (t&7)*8 (transpose)
    int kb = tid >> 3;
    int nb0 = (tid & 7) * 8;

    for (int k0 = 0; k0 < K; k0 += BK) {
        {
            const float* ap = A + (size_t)grow * K + k0 + acol0;
            unsigned hw[8];
#pragma unroll
            for (int j = 0; j < 4; j++) {
                float4 v = (grow < M) ? *(const float4*)(ap + j * 4)
                                      : make_float4(0.f, 0.f, 0.f, 0.f);
                __half2 h01 = __floats2half2_rn(v.x, v.y);
                __half2 h23 = __floats2half2_rn(v.z, v.w);
                hw[j * 2 + 0] = *reinterpret_cast<unsigned*>(&h01);
                hw[j * 2 + 1] = *reinterpret_cast<unsigned*>(&h23);
            }
            uint4* dst = reinterpret_cast<uint4*>(&As[arow][acol0]);
            dst[0] = make_uint4(hw[0], hw[1], hw[2], hw[3]);
            dst[1] = make_uint4(hw[4], hw[5], hw[6], hw[7]);
        }
        {
            const float* bp = B + (size_t)(k0 + kb) * Nc + bn0 + nb0;
            float4 v0 = *(const float4*)bp;
            float4 v1 = *(const float4*)(bp + 4);
            Bs[nb0 + 0][kb] = __float2half_rn(v0.x);
            Bs[nb0 + 1][kb] = __float2half_rn(v0.y);
            Bs[nb0 + 2][kb] = __float2half_rn(v0.z);
            Bs[nb0 + 3][kb] = __float2half_rn(v0.w);
            Bs[nb0 + 4][kb] = __float2half_rn(v1.x);
            Bs[nb0 + 5][kb] = __float2half_rn(v1.y);
            Bs[nb0 + 6][kb] = __float2half_rn(v1.z);
            Bs[nb0 + 7][kb] = __float2half_rn(v1.w);
        }
        __syncthreads();

#pragma unroll
        for (int kk = 0; kk < BK; kk += 16) {
            int gr = lane >> 2;
            int kq = kk + (lane & 3) * 2;
            unsigned afr[2][4];
#pragma unroll
            for (int mt = 0; mt < 2; mt++) {
                int rb = wm * 32 + mt * 16 + gr;
                afr[mt][0] = *(const unsigned*)&As[rb][kq];
                afr[mt][1] = *(const unsigned*)&As[rb + 8][kq];
                afr[mt][2] = *(const unsigned*)&As[rb][kq + 8];
                afr[mt][3] = *(const unsigned*)&As[rb + 8][kq + 8];
            }
            unsigned bfr[4][2];
#pragma unroll
            for (int nt = 0; nt < 4; nt++) {
                int nb = wn * 32 + nt * 8 + gr;
                bfr[nt][0] = *(const unsigned*)&Bs[nb][kq];
                bfr[nt][1] = *(const unsigned*)&Bs[nb][kq + 8];
            }
#pragma unroll
            for (int mt = 0; mt < 2; mt++)
#pragma unroll
                for (int nt = 0; nt < 4; nt++) {
                    asm volatile(
                        "mma.sync.aligned.m16n8k16.row.col.f32.f16.f16.f32 "
                        "{%0,%1,%2,%3}, {%4,%5,%6,%7}, {%8,%9}, {%0,%1,%2,%3};"
                        : "+f"(acc[mt][nt][0]), "+f"(acc[mt][nt][1]),
                          "+f"(acc[mt][nt][2]), "+f"(acc[mt][nt][3])
                        : "r"(afr[mt][0]), "r"(afr[mt][1]), "r"(afr[mt][2]), "r"(afr[mt][3]),
                          "r"(bfr[nt][0]), "r"(bfr[nt][1]));
                }
        }
        __syncthreads();
    }

    // epilogue: fp32 acc -> fp16 stores (same c-fragment mapping as m16n8k8)
#pragma unroll
    for (int mt = 0; mt < 2; mt++) {
        int r = bm0 + wm * 32 + mt * 16 + (lane >> 2);
#pragma unroll
        for (int nt = 0; nt < 4; nt++) {
            int c = bn0 + wn * 32 + nt * 8 + (lane & 3) * 2;
            if (r < M) {
                __half2 v0 = __floats2half2_rn(acc[mt][nt][0], acc[mt][nt][1]);
                *(__half2*)(C + (size_t)r * Nc + c) = v0;
            }
            if (r + 8 < M) {
                __half2 v1 = __floats2half2_rn(acc[mt][nt][2], acc[mt][nt][3]);
                *(__half2*)(C + (size_t)(r + 8) * Nc + c) = v1;
            }
        }
    }
}

// ---------------- dots + fused global max: g_als/g_ald [N,H], g_mxals[LAYER] ----------------
template <int H, int C, int LAYER>
__global__ void k_dots(const float* __restrict__ a_src, const float* __restrict__ a_dst, int n) {
    constexpr int D = H * C;
    constexpr int CPL = D / 32;
    constexpr int G = 32 / H;
    int wid = threadIdx.x >> 5;
    int lane = threadIdx.x & 31;
    int node = blockIdx.x * 4 + wid;
    bool valid = node < n;

    float ss = 0.f, sd = 0.f;
    int c0 = lane * CPL;
    if (valid) {
        float hv[CPL];
        const __half* hr = g_h + (size_t)node * D + c0;
        if (CPL == 4) {
            uint2 raw = *(const uint2*)hr;
            float2 f01 = __half22float2(*reinterpret_cast<__half2*>(&raw.x));
            float2 f23 = __half22float2(*reinterpret_cast<__half2*>(&raw.y));
            hv[0] = f01.x; hv[1] = f01.y; hv[2] = f23.x; hv[3] = f23.y;
        } else {
            unsigned raw = *(const unsigned*)hr;
            float2 f01 = __half22float2(*reinterpret_cast<__half2*>(&raw));
            hv[0] = f01.x; hv[1] = f01.y;
        }
#pragma unroll
        for (int j = 0; j < CPL; j++) {
            ss = fmaf(hv[j], a_src[c0 + j], ss);
            sd = fmaf(hv[j], a_dst[c0 + j], sd);
        }
    }
#pragma unroll
    for (int o = G / 2; o > 0; o >>= 1) {
        ss += __shfl_down_sync(0xffffffffu, ss, o, G);
        sd += __shfl_down_sync(0xffffffffu, sd, o, G);
    }
    __shared__ float smax[4][H];
    if ((lane % G) == 0) {
        int hd = lane / G;
        if (valid) {
            g_als[(size_t)node * H + hd] = ss;
            g_ald[(size_t)node * H + hd] = sd;
        }
        smax[wid][hd] = valid ? ss : -1e30f;
    }
    __syncthreads();
    if (threadIdx.x < H) {
        float m = smax[0][threadIdx.x];
#pragma unroll
        for (int ww = 1; ww < 4; ww++) m = fmaxf(m, smax[ww][threadIdx.x]);
        atomicMax(&g_mxals[LAYER][threadIdx.x], fenc(m));
    }
}

// ---------------- fused segment softmax + weighted aggregate (unrolled x4) ----------------
template <int H, int C, bool RELU, int LAYER>
__global__ void k_aggregate(const float* __restrict__ bias, float* __restrict__ outExt, int n) {
    constexpr int D = H * C;
    constexpr int CPL = D / 32;
    constexpr int G = 32 / H;
    float* __restrict__ out = outExt ? outExt : g_act;
    int wid = threadIdx.x >> 5;
    int lane = threadIdx.x & 31;
    int node = blockIdx.x * 4 + wid;
    if (node >= n) return;

    int s0 = g_rowptr[node];
    int s1 = g_rowptr[node + 1];

    int c0 = lane * CPL;
    int hd = lane / G;
    float myald = g_ald[(size_t)node * H + hd];
    float Mh = fdec(g_mxals[LAYER][hd]);
    float mymx = Mh + myald;
    mymx = (mymx > 0.f) ? mymx : SLOPE * mymx;

    float acc[CPL];
#pragma unroll
    for (int j = 0; j < CPL; j++) acc[j] = 0.f;
    float esum = 0.f;

    int i = s0;
    for (; i + 4 <= s1; i += 4) {
        int2 p0 = g_csr[i + 0];
        int2 p1 = g_csr[i + 1];
        int2 p2 = g_csr[i + 2];
        int2 p3 = g_csr[i + 3];
        float a0 = g_als[(size_t)p0.x * H + hd];
        float a1 = g_als[(size_t)p1.x * H + hd];
        float a2 = g_als[(size_t)p2.x * H + hd];
        float a3 = g_als[(size_t)p3.x * H + hd];
        if (CPL == 4) {
            uint2 r0 = *(const uint2*)(g_h + (size_t)p0.x * D + c0);
            uint2 r1 = *(const uint2*)(g_h + (size_t)p1.x * D + c0);
            uint2 r2 = *(const uint2*)(g_h + (size_t)p2.x * D + c0);
            uint2 r3 = *(const uint2*)(g_h + (size_t)p3.x * D + c0);
            float l0 = a0 + myald; l0 = (l0 > 0.f) ? l0 : SLOPE * l0;
            float l1 = a1 + myald; l1 = (l1 > 0.f) ? l1 : SLOPE * l1;
            float l2 = a2 + myald; l2 = (l2 > 0.f) ? l2 : SLOPE * l2;
            float l3 = a3 + myald; l3 = (l3 > 0.f) ? l3 : SLOPE * l3;
            float e0 = __expf(l0 - mymx) * __int_as_float(p0.y);
            float e1 = __expf(l1 - mymx) * __int_as_float(p1.y);
            float e2 = __expf(l2 - mymx) * __int_as_float(p2.y);
            float e3 = __expf(l3 - mymx) * __int_as_float(p3.y);
            esum += (e0 + e1) + (e2 + e3);
            float2 f;
            f = __half22float2(*reinterpret_cast<__half2*>(&r0.x));
            acc[0] = fmaf(e0, f.x, acc[0]); acc[1] = fmaf(e0, f.y, acc[1]);
            f = __half22float2(*reinterpret_cast<__half2*>(&r0.y));
            acc[2] = fmaf(e0, f.x, acc[2]); acc[3] = fmaf(e0, f.y, acc[3]);
            f = __half22float2(*reinterpret_cast<__half2*>(&r1.x));
            acc[0] = fmaf(e1, f.x, acc[0]); acc[1] = fmaf(e1, f.y, acc[1]);
            f = __half22float2(*reinterpret_cast<__half2*>(&r1.y));
            acc[2] = fmaf(e1, f.x, acc[2]); acc[3] = fmaf(e1, f.y, acc[3]);
            f = __half22float2(*reinterpret_cast<__half2*>(&r2.x));
            acc[0] = fmaf(e2, f.x, acc[0]); acc[1] = fmaf(e2, f.y, acc[1]);
            f = __half22float2(*reinterpret_cast<__half2*>(&r2.y));
            acc[2] = fmaf(e2, f.x, acc[2]); acc[3] = fmaf(e2, f.y, acc[3]);
            f = __half22float2(*reinterpret_cast<__half2*>(&r3.x));
            acc[0] = fmaf(e3, f.x, acc[0]); acc[1] = fmaf(e3, f.y, acc[1]);
            f = __half22float2(*reinterpret_cast<__half2*>(&r3.y));
            acc[2] = fmaf(e3, f.x, acc[2]); acc[3] = fmaf(e3, f.y, acc[3]);
        } else {
            unsigned r0 = *(const unsigned*)(g_h + (size_t)p0.x * D + c0);
            unsigned r1 = *(const unsigned*)(g_h + (size_t)p1.x * D + c0);
            unsigned r2 = *(const unsigned*)(g_h + (size_t)p2.x * D + c0);
            unsigned r3 = *(const unsigned*)(g_h + (size_t)p3.x * D + c0);
            float l0 = a0 + myald; l0 = (l0 > 0.f) ? l0 : SLOPE * l0;
            float l1 = a1 + myald; l1 = (l1 > 0.f) ? l1 : SLOPE * l1;
            float l2 = a2 + myald; l2 = (l2 > 0.f) ? l2 : SLOPE * l2;
            float l3 = a3 + myald; l3 = (l3 > 0.f) ? l3 : SLOPE * l3;
            float e0 = __expf(l0 - mymx) * __int_as_float(p0.y);
            float e1 = __expf(l1 - mymx) * __int_as_float(p1.y);
            float e2 = __expf(l2 - mymx) * __int_as_float(p2.y);
            float e3 = __expf(l3 - mymx) * __int_as_float(p3.y);
            esum += (e0 + e1) + (e2 + e3);
            float2 f;
            f = __half22float2(*reinterpret_cast<__half2*>(&r0));
            acc[0] = fmaf(e0, f.x, acc[0]); acc[1] = fmaf(e0, f.y, acc[1]);
            f = __half22float2(*reinterpret_cast<__half2*>(&r1));
            acc[0] = fmaf(e1, f.x, acc[0]); acc[1] = fmaf(e1, f.y, acc[1]);
            f = __half22float2(*reinterpret_cast<__half2*>(&r2));
            acc[0] = fmaf(e2, f.x, acc[0]); acc[1] = fmaf(e2, f.y, acc[1]);
            f = __half22float2(*reinterpret_cast<__half2*>(&r3));
            acc[0] = fmaf(e3, f.x, acc[0]); acc[1] = fmaf(e3, f.y, acc[1]);
        }
    }
    for (; i < s1; i++) {
        int2 p = g_csr[i];
        float l = g_als[(size_t)p.x * H + hd] + myald;
        l = (l > 0.f) ? l : SLOPE * l;
        float e = __expf(l - mymx) * __int_as_float(p.y);
        esum += e;
        const __half* hp = g_h + (size_t)p.x * D + c0;
        if (CPL == 4) {
            uint2 raw = *(const uint2*)hp;
            float2 f01 = __half22float2(*reinterpret_cast<__half2*>(&raw.x));
            float2 f23 = __half22float2(*reinterpret_cast<__half2*>(&raw.y));
            acc[0] = fmaf(e, f01.x, acc[0]);
            acc[1] = fmaf(e, f01.y, acc[1]);
            acc[2] = fmaf(e, f23.x, acc[2]);
            acc[3] = fmaf(e, f23.y, acc[3]);
        } else {
            unsigned raw = *(const unsigned*)hp;
            float2 f01 = __half22float2(*reinterpret_cast<__half2*>(&raw));
            acc[0] = fmaf(e, f01.x, acc[0]);
            acc[1] = fmaf(e, f01.y, acc[1]);
        }
    }
    float inv = 1.0f / (esum + 1e-16f);
#pragma unroll
    for (int j = 0; j < CPL; j++) {
        float v = fmaf(acc[j], inv, bias[c0 + j]);
        if (RELU) v = fmaxf(v, 0.f);
        out[(size_t)node * D + c0 + j] = v;
    }
}

// ---------------- host launch ----------------
extern "C" void kernel_launch(void* const* d_in, const int* in_sizes, int n_in,
                              void* d_out, int out_size) {
    const float* x   = (const float*)d_in[0];
    const void*  ei  = d_in[1];
    const float* ew  = (const float*)d_in[2];
    const float* W1  = (const float*)d_in[3];
    const float* aS1 = (const float*)d_in[4];
    const float* aD1 = (const float*)d_in[5];
    const float* b1  = (const float*)d_in[6];
    const float* W2  = (const float*)d_in[7];
    const float* aS2 = (const float*)d_in[8];
    const float* aD2 = (const float*)d_in[9];
    const float* b2  = (const float*)d_in[10];
    const float* W3  = (const float*)d_in[11];
    const float* aS3 = (const float*)d_in[12];
    const float* aD3 = (const float*)d_in[13];
    const float* b3  = (const float*)d_in[14];

    const int E = in_sizes[2];
    const int n = NN;

    const int nodeBlocks = (n + 3) / 4;
    dim3 gemmGrid2(D1 / 64, (n + 127) / 128);
    dim3 gemmGrid1(OUT_F / 64, (n + 127) / 128);

    // CSR build + layer-1 GEMM interleaved; GEMM placed 4th so ncu profiles it.
    k_detect_zero<<<(n + 255) / 256, 256>>>(ei, E, n);            // 1
    k_count_deg<<<(E + 255) / 256, 256>>>(ei, E, n);              // 2
    k_scan1<<<NBLK, SCAN_B>>>(n);                                  // 3
    k_gemm_f16<<<gemmGrid2, 256>>>(x, W1, n, IN_F, D1);           // 4  <- profiled
    k_scan2<<<1, 64>>>();                                          // 5
    k_scan3<<<(n + 255) / 256, 256>>>(n);                          // 6
    k_scatter<<<(E + 255) / 256, 256>>>(ei, ew, E, n);             // 7

    // Layer 1: 256 -> 128, H=4, C=32, relu
    k_dots<4, 32, 0><<<nodeBlocks, 128>>>(aS1, aD1, n);
    k_aggregate<4, 32, true, 0><<<nodeBlocks, 128>>>(b1, nullptr, n);

    // Layer 2: 128 -> 128, H=4, C=32, relu
    k_gemm_f16<<<gemmGrid2, 256>>>(nullptr, W2, n, D1, D1);
    k_dots<4, 32, 1><<<nodeBlocks, 128>>>(aS2, aD2, n);
    k_aggregate<4, 32, true, 1><<<nodeBlocks, 128>>>(b2, nullptr, n);

    // Layer 3: 128 -> 64, H=1, C=64, no relu
    k_gemm_f16<<<gemmGrid1, 256>>>(nullptr, W3, n, D1, OUT_F);
    k_dots<1, 64, 2><<<nodeBlocks, 128>>>(aS3, aD3, n);
    k_aggregate<1, 64, false, 2><<<nodeBlocks, 128>>>(b3, (float*)d_out, n);
}

// round 14
// speedup vs baseline: 1.1012x; 1.1012x over previous
#include <cuda_runtime.h>
#include <cuda_fp16.h>
#include <math.h>

// Problem constants (match reference)
#define NN 50000
#define NE 800000
#define IN_F 256
#define D1 128      // HEADS*HID
#define OUT_F 64
#define SLOPE 0.2f

#define SCAN_B 1024
#define NBLK ((NN + SCAN_B - 1) / SCAN_B)   // 49

// ---------------- device scratch (no allocations allowed) ----------------
__device__ __align__(16) __half g_h[(size_t)NN * D1];    // GEMM output, fp16 (gather path)
__device__ __align__(16) float  g_act[(size_t)NN * D1];  // post-aggregate activations, fp32
__device__ __align__(16) float  g_als[(size_t)NN * 4];
__device__ __align__(16) float  g_ald[(size_t)NN * 4];
__device__ int   g_rowptr[NN + 1];
__device__ int   g_deg[NN];
__device__ int   g_cursor[NN];
__device__ __align__(8) int2 g_csr[NE];    // (src, weight-bits) packed
__device__ int   g_bsum[NBLK];
__device__ int   g_boff[NBLK];
__device__ unsigned g_mxals[3][4];         // per-layer per-head global max(als), int-encoded
__device__ int   g_idx64;

// monotone float<->uint encoding for atomicMax on floats (0u acts as -inf)
__device__ __forceinline__ unsigned fenc(float f) {
    int b = __float_as_int(f);
    return (b >= 0) ? ((unsigned)b | 0x80000000u) : ~(unsigned)b;
}
__device__ __forceinline__ float fdec(unsigned u) {
    int b = (u & 0x80000000u) ? (int)(u & 0x7fffffffu) : ~(int)u;
    return __int_as_float(b);
}

// round-to-nearest tf32 conversion — REQUIRED (raw bits => biased truncation).
__device__ __forceinline__ unsigned f2tf(float f) {
    unsigned u;
    asm("cvt.rna.tf32.f32 %0, %1;" : "=r"(u) : "f"(f));
    return u;
}

// ---------------- fused: zero deg + dtype detect (block 0) ----------------
__global__ void k_detect_zero(const void* ei_raw, int E, int n) {
    int i = blockIdx.x * blockDim.x + threadIdx.x;
    if (i < n) g_deg[i] = 0;
    if (blockIdx.x == 0) {
        __shared__ int ok;
        if (threadIdx.x == 0) ok = 1;
        __syncthreads();
        const long long* p = (const long long*)ei_raw;
        int nchk = 2 * E < 256 ? 2 * E : 256;
        if (threadIdx.x < nchk) {
            long long v = p[threadIdx.x];
            if (v < 0 || v >= NN) atomicAnd(&ok, 0);
        }
        __syncthreads();
        if (threadIdx.x == 0) g_idx64 = ok;
    }
}

__device__ __forceinline__ void load_edge(const void* ei_raw, int E, int e, int idx64,
                                          int& s, int& d) {
    if (idx64) {
        const long long* p = (const long long*)ei_raw;
        s = (int)p[e];
        d = (int)p[E + e];
    } else {
        const int* p = (const int*)ei_raw;
        s = p[e];
        d = p[E + e];
    }
}

// ---------------- CSR construction ----------------
__global__ void k_count_deg(const void* ei_raw, int E, int n) {
    int e = blockIdx.x * blockDim.x + threadIdx.x;
    int idx64 = g_idx64;
    if (e < E) {
        int s, d;
        load_edge(ei_raw, E, e, idx64, s, d);
        if (d >= 0 && d < n) atomicAdd(&g_deg[d], 1);
    }
}

__global__ void k_scan1(int n) {
    int t = threadIdx.x;
    int i = blockIdx.x * SCAN_B + t;
    int lane = t & 31, w = t >> 5;
    int v = (i < n) ? g_deg[i] : 0;
    int x = v;
#pragma unroll
    for (int o = 1; o < 32; o <<= 1) {
        int y = __shfl_up_sync(0xffffffffu, x, o);
        if (lane >= o) x += y;
    }
    __shared__ int ws[32];
    if (lane == 31) ws[w] = x;
    __syncthreads();
    if (w == 0) {
        int y = ws[lane];
#pragma unroll
        for (int o = 1; o < 32; o <<= 1) {
            int z = __shfl_up_sync(0xffffffffu, y, o);
            if (lane >= o) y += z;
        }
        ws[lane] = y;
    }
    __syncthreads();
    int incl = x + (w > 0 ? ws[w - 1] : 0);
    if (i < n) g_rowptr[i + 1] = incl;
    if (t == SCAN_B - 1) g_bsum[blockIdx.x] = incl;
}

__global__ void k_scan2() {
    int t = threadIdx.x;
    int lane = t & 31, w = t >> 5;
    if (t < 12) ((unsigned*)g_mxals)[t] = 0u;    // init per-layer max slots
    int v = (t < NBLK) ? g_bsum[t] : 0;
    int x = v;
#pragma unroll
    for (int o = 1; o < 32; o <<= 1) {
        int y = __shfl_up_sync(0xffffffffu, x, o);
        if (lane >= o) x += y;
    }
    __shared__ int ws[2];
    if (lane == 31) ws[w] = x;
    __syncthreads();
    int incl = x + (w > 0 ? ws[0] : 0);
    if (t < NBLK) g_boff[t] = incl - v;
}

__global__ void k_scan3(int n) {
    int i = blockIdx.x * blockDim.x + threadIdx.x;
    if (i < n) {
        int incl = g_rowptr[i + 1] + g_boff[i >> 10];
        g_rowptr[i + 1] = incl;
        g_cursor[i] = incl - g_deg[i];
        if (i == 0) g_rowptr[0] = 0;
    }
}

__global__ void k_scatter(const void* ei_raw, const float* __restrict__ ew, int E, int n) {
    int e = blockIdx.x * blockDim.x + threadIdx.x;
    int idx64 = g_idx64;
    if (e < E) {
        int s, d;
        load_edge(ei_raw, E, e, idx64, s, d);
        if (s >= 0 && s < n && d >= 0 && d < n) {
            int pos = atomicAdd(&g_cursor[d], 1);
            if (pos >= 0 && pos < E) {
                g_csr[pos] = make_int2(s, __float_as_int(ew[e]));
            }
        }
    }
}

// ---------------- TF32 tensor-core GEMM (round-12 proven config) ----------------
// g_h[M,Nc] (fp16) = A[M,K] @ B[K,Nc].  BM=128, BN=64, BK=32, 8 warps, warp tile 32x32.
__global__ __launch_bounds__(256)
void k_gemm_tf32(const float* __restrict__ Aext, const float* __restrict__ B,
                 int M, int K, int Nc) {
    constexpr int BM = 128, BN = 64, BK = 32;
    constexpr int APAD = 36;
    constexpr int BPAD = 72;
    __shared__ __align__(16) unsigned As[BM][APAD];
    __shared__ __align__(16) unsigned Bs[BK][BPAD];

    const float* __restrict__ A = Aext ? Aext : g_act;
    __half* __restrict__ C = g_h;

    int tid = threadIdx.x;
    int lane = tid & 31;
    int warp = tid >> 5;
    int wm = warp >> 1;
    int wn = warp & 1;
    int bm0 = blockIdx.y * BM;
    int bn0 = blockIdx.x * BN;

    float acc[2][4][4];
#pragma unroll
    for (int mt = 0; mt < 2; mt++)
#pragma unroll
        for (int nt = 0; nt < 4; nt++)
#pragma unroll
            for (int i = 0; i < 4; i++) acc[mt][nt][i] = 0.f;

    int arow = tid >> 1;
    int acol0 = (tid & 1) * 16;
    int brow = tid >> 3;
    int bcol0 = (tid & 7) * 4;
    int grow = bm0 + arow;

    for (int k0 = 0; k0 < K; k0 += BK) {
        const float* ap = A + (size_t)grow * K + k0 + acol0;
#pragma unroll
        for (int j = 0; j < 4; j++) {
            float4 v = (grow < M) ? *(const float4*)(ap + j * 4)
                                  : make_float4(0.f, 0.f, 0.f, 0.f);
            unsigned* dstp = &As[arow][acol0 + j * 4];
            dstp[0] = f2tf(v.x); dstp[1] = f2tf(v.y);
            dstp[2] = f2tf(v.z); dstp[3] = f2tf(v.w);
        }
        const float* bp = B + (size_t)(k0 + brow) * Nc + bn0;
#pragma unroll
        for (int it = 0; it < 2; it++) {
            float4 v = *(const float4*)(bp + bcol0 + it * 32);
            unsigned* dstp = &Bs[brow][bcol0 + it * 32];
            dstp[0] = f2tf(v.x); dstp[1] = f2tf(v.y);
            dstp[2] = f2tf(v.z); dstp[3] = f2tf(v.w);
        }
        __syncthreads();

#pragma unroll
        for (int kc = 0; kc < BK; kc += 8) {
            unsigned afr[2][4];
            int r0 = wm * 32 + (lane >> 2);
            int cA = kc + (lane & 3);
#pragma unroll
            for (int mt = 0; mt < 2; mt++) {
                int rb = r0 + mt * 16;
                afr[mt][0] = As[rb][cA];
                afr[mt][1] = As[rb + 8][cA];
                afr[mt][2] = As[rb][cA + 4];
                afr[mt][3] = As[rb + 8][cA + 4];
            }
            unsigned bfr[4][2];
            int kB0 = kc + (lane & 3);
            int nB0 = wn * 32 + (lane >> 2);
#pragma unroll
            for (int nt = 0; nt < 4; nt++) {
                bfr[nt][0] = Bs[kB0][nB0 + nt * 8];
                bfr[nt][1] = Bs[kB0 + 4][nB0 + nt * 8];
            }
#pragma unroll
            for (int mt = 0; mt < 2; mt++)
#pragma unroll
                for (int nt = 0; nt < 4; nt++) {
                    asm volatile(
                        "mma.sync.aligned.m16n8k8.row.col.f32.tf32.tf32.f32 "
                        "{%0,%1,%2,%3}, {%4,%5,%6,%7}, {%8,%9}, {%0,%1,%2,%3};"
                        : "+f"(acc[mt][nt][0]), "+f"(acc[mt][nt][1]),
                          "+f"(acc[mt][nt][2]), "+f"(acc[mt][nt][3])
                        : "r"(afr[mt][0]), "r"(afr[mt][1]), "r"(afr[mt][2]), "r"(afr[mt][3]),
                          "r"(bfr[nt][0]), "r"(bfr[nt][1]));
                }
        }
        __syncthreads();
    }

    // epilogue: fp32 acc -> fp16 stores
#pragma unroll
    for (int mt = 0; mt < 2; mt++) {
        int r = bm0 + wm * 32 + mt * 16 + (lane >> 2);
#pragma unroll
        for (int nt = 0; nt < 4; nt++) {
            int c = bn0 + wn * 32 + nt * 8 + (lane & 3) * 2;
            if (r < M) {
                __half2 v0 = __floats2half2_rn(acc[mt][nt][0], acc[mt][nt][1]);
                *(__half2*)(C + (size_t)r * Nc + c) = v0;
            }
            if (r + 8 < M) {
                __half2 v1 = __floats2half2_rn(acc[mt][nt][2], acc[mt][nt][3]);
                *(__half2*)(C + (size_t)(r + 8) * Nc + c) = v1;
            }
        }
    }
}

// ---------------- dots + fused global max ----------------
template <int H, int C, int LAYER>
__global__ void k_dots(const float* __restrict__ a_src, const float* __restrict__ a_dst, int n) {
    constexpr int D = H * C;
    constexpr int CPL = D / 32;
    constexpr int G = 32 / H;
    int wid = threadIdx.x >> 5;
    int lane = threadIdx.x & 31;
    int node = blockIdx.x * 4 + wid;
    bool valid = node < n;

    float ss = 0.f, sd = 0.f;
    int c0 = lane * CPL;
    if (valid) {
        float hv[CPL];
        const __half* hr = g_h + (size_t)node * D + c0;
        if (CPL == 4) {
            uint2 raw = *(const uint2*)hr;
            float2 f01 = __half22float2(*reinterpret_cast<__half2*>(&raw.x));
            float2 f23 = __half22float2(*reinterpret_cast<__half2*>(&raw.y));
            hv[0] = f01.x; hv[1] = f01.y; hv[2] = f23.x; hv[3] = f23.y;
        } else {
            unsigned raw = *(const unsigned*)hr;
            float2 f01 = __half22float2(*reinterpret_cast<__half2*>(&raw));
            hv[0] = f01.x; hv[1] = f01.y;
        }
#pragma unroll
        for (int j = 0; j < CPL; j++) {
            ss = fmaf(hv[j], a_src[c0 + j], ss);
            sd = fmaf(hv[j], a_dst[c0 + j], sd);
        }
    }
#pragma unroll
    for (int o = G / 2; o > 0; o >>= 1) {
        ss += __shfl_down_sync(0xffffffffu, ss, o, G);
        sd += __shfl_down_sync(0xffffffffu, sd, o, G);
    }
    __shared__ float smax[4][H];
    if ((lane % G) == 0) {
        int hd = lane / G;
        if (valid) {
            g_als[(size_t)node * H + hd] = ss;
            g_ald[(size_t)node * H + hd] = sd;
        }
        smax[wid][hd] = valid ? ss : -1e30f;
    }
    __syncthreads();
    if (threadIdx.x < H) {
        float m = smax[0][threadIdx.x];
#pragma unroll
        for (int ww = 1; ww < 4; ww++) m = fmaxf(m, smax[ww][threadIdx.x]);
        atomicMax(&g_mxals[LAYER][threadIdx.x], fenc(m));
    }
}

// ---------------- fused segment softmax + weighted aggregate (unrolled x4) ----------------
template <int H, int C, bool RELU, int LAYER>
__global__ void k_aggregate(const float* __restrict__ bias, float* __restrict__ outExt, int n) {
    constexpr int D = H * C;
    constexpr int CPL = D / 32;
    constexpr int G = 32 / H;
    float* __restrict__ out = outExt ? outExt : g_act;
    int wid = threadIdx.x >> 5;
    int lane = threadIdx.x & 31;
    int node = blockIdx.x * 4 + wid;
    if (node >= n) return;

    int s0 = g_rowptr[node];
    int s1 = g_rowptr[node + 1];

    int c0 = lane * CPL;
    int hd = lane / G;
    float myald = g_ald[(size_t)node * H + hd];
    float Mh = fdec(g_mxals[LAYER][hd]);
    float mymx = Mh + myald;
    mymx = (mymx > 0.f) ? mymx : SLOPE * mymx;

    float acc[CPL];
#pragma unroll
    for (int j = 0; j < CPL; j++) acc[j] = 0.f;
    float esum = 0.f;

    int i = s0;
    for (; i + 4 <= s1; i += 4) {
        int2 p0 = g_csr[i + 0];
        int2 p1 = g_csr[i + 1];
        int2 p2 = g_csr[i + 2];
        int2 p3 = g_csr[i + 3];
        float a0 = g_als[(size_t)p0.x * H + hd];
        float a1 = g_als[(size_t)p1.x * H + hd];
        float a2 = g_als[(size_t)p2.x * H + hd];
        float a3 = g_als[(size_t)p3.x * H + hd];
        if (CPL == 4) {
            uint2 r0 = *(const uint2*)(g_h + (size_t)p0.x * D + c0);
            uint2 r1 = *(const uint2*)(g_h + (size_t)p1.x * D + c0);
            uint2 r2 = *(const uint2*)(g_h + (size_t)p2.x * D + c0);
            uint2 r3 = *(const uint2*)(g_h + (size_t)p3.x * D + c0);
            float l0 = a0 + myald; l0 = (l0 > 0.f) ? l0 : SLOPE * l0;
            float l1 = a1 + myald; l1 = (l1 > 0.f) ? l1 : SLOPE * l1;
            float l2 = a2 + myald; l2 = (l2 > 0.f) ? l2 : SLOPE * l2;
            float l3 = a3 + myald; l3 = (l3 > 0.f) ? l3 : SLOPE * l3;
            float e0 = __expf(l0 - mymx) * __int_as_float(p0.y);
            float e1 = __expf(l1 - mymx) * __int_as_float(p1.y);
            float e2 = __expf(l2 - mymx) * __int_as_float(p2.y);
            float e3 = __expf(l3 - mymx) * __int_as_float(p3.y);
            esum += (e0 + e1) + (e2 + e3);
            float2 f;
            f = __half22float2(*reinterpret_cast<__half2*>(&r0.x));
            acc[0] = fmaf(e0, f.x, acc[0]); acc[1] = fmaf(e0, f.y, acc[1]);
            f = __half22float2(*reinterpret_cast<__half2*>(&r0.y));
            acc[2] = fmaf(e0, f.x, acc[2]); acc[3] = fmaf(e0, f.y, acc[3]);
            f = __half22float2(*reinterpret_cast<__half2*>(&r1.x));
            acc[0] = fmaf(e1, f.x, acc[0]); acc[1] = fmaf(e1, f.y, acc[1]);
            f = __half22float2(*reinterpret_cast<__half2*>(&r1.y));
            acc[2] = fmaf(e1, f.x, acc[2]); acc[3] = fmaf(e1, f.y, acc[3]);
            f = __half22float2(*reinterpret_cast<__half2*>(&r2.x));
            acc[0] = fmaf(e2, f.x, acc[0]); acc[1] = fmaf(e2, f.y, acc[1]);
            f = __half22float2(*reinterpret_cast<__half2*>(&r2.y));
            acc[2] = fmaf(e2, f.x, acc[2]); acc[3] = fmaf(e2, f.y, acc[3]);
            f = __half22float2(*reinterpret_cast<__half2*>(&r3.x));
            acc[0] = fmaf(e3, f.x, acc[0]); acc[1] = fmaf(e3, f.y, acc[1]);
            f = __half22float2(*reinterpret_cast<__half2*>(&r3.y));
            acc[2] = fmaf(e3, f.x, acc[2]); acc[3] = fmaf(e3, f.y, acc[3]);
        } else {
            unsigned r0 = *(const unsigned*)(g_h + (size_t)p0.x * D + c0);
            unsigned r1 = *(const unsigned*)(g_h + (size_t)p1.x * D + c0);
            unsigned r2 = *(const unsigned*)(g_h + (size_t)p2.x * D + c0);
            unsigned r3 = *(const unsigned*)(g_h + (size_t)p3.x * D + c0);
            float l0 = a0 + myald; l0 = (l0 > 0.f) ? l0 : SLOPE * l0;
            float l1 = a1 + myald; l1 = (l1 > 0.f) ? l1 : SLOPE * l1;
            float l2 = a2 + myald; l2 = (l2 > 0.f) ? l2 : SLOPE * l2;
            float l3 = a3 + myald; l3 = (l3 > 0.f) ? l3 : SLOPE * l3;
            float e0 = __expf(l0 - mymx) * __int_as_float(p0.y);
            float e1 = __expf(l1 - mymx) * __int_as_float(p1.y);
            float e2 = __expf(l2 - mymx) * __int_as_float(p2.y);
            float e3 = __expf(l3 - mymx) * __int_as_float(p3.y);
            esum += (e0 + e1) + (e2 + e3);
            float2 f;
            f = __half22float2(*reinterpret_cast<__half2*>(&r0));
            acc[0] = fmaf(e0, f.x, acc[0]); acc[1] = fmaf(e0, f.y, acc[1]);
            f = __half22float2(*reinterpret_cast<__half2*>(&r1));
            acc[0] = fmaf(e1, f.x, acc[0]); acc[1] = fmaf(e1, f.y, acc[1]);
            f = __half22float2(*reinterpret_cast<__half2*>(&r2));
            acc[0] = fmaf(e2, f.x, acc[0]); acc[1] = fmaf(e2, f.y, acc[1]);
            f = __half22float2(*reinterpret_cast<__half2*>(&r3));
            acc[0] = fmaf(e3, f.x, acc[0]); acc[1] = fmaf(e3, f.y, acc[1]);
        }
    }
    for (; i < s1; i++) {
        int2 p = g_csr[i];
        float l = g_als[(size_t)p.x * H + hd] + myald;
        l = (l > 0.f) ? l : SLOPE * l;
        float e = __expf(l - mymx) * __int_as_float(p.y);
        esum += e;
        const __half* hp = g_h + (size_t)p.x * D + c0;
        if (CPL == 4) {
            uint2 raw = *(const uint2*)hp;
            float2 f01 = __half22float2(*reinterpret_cast<__half2*>(&raw.x));
            float2 f23 = __half22float2(*reinterpret_cast<__half2*>(&raw.y));
            acc[0] = fmaf(e, f01.x, acc[0]);
            acc[1] = fmaf(e, f01.y, acc[1]);
            acc[2] = fmaf(e, f23.x, acc[2]);
            acc[3] = fmaf(e, f23.y, acc[3]);
        } else {
            unsigned raw = *(const unsigned*)hp;
            float2 f01 = __half22float2(*reinterpret_cast<__half2*>(&raw));
            acc[0] = fmaf(e, f01.x, acc[0]);
            acc[1] = fmaf(e, f01.y, acc[1]);
        }
    }
    float inv = 1.0f / (esum + 1e-16f);
#pragma unroll
    for (int j = 0; j < CPL; j++) {
        float v = fmaf(acc[j], inv, bias[c0 + j]);
        if (RELU) v = fmaxf(v, 0.f);
        out[(size_t)node * D + c0 + j] = v;
    }
}

// ---------------- host launch ----------------
extern "C" void kernel_launch(void* const* d_in, const int* in_sizes, int n_in,
                              void* d_out, int out_size) {
    const float* x   = (const float*)d_in[0];
    const void*  ei  = d_in[1];
    const float* ew  = (const float*)d_in[2];
    const float* W1  = (const float*)d_in[3];
    const float* aS1 = (const float*)d_in[4];
    const float* aD1 = (const float*)d_in[5];
    const float* b1  = (const float*)d_in[6];
    const float* W2  = (const float*)d_in[7];
    const float* aS2 = (const float*)d_in[8];
    const float* aD2 = (const float*)d_in[9];
    const float* b2  = (const float*)d_in[10];
    const float* W3  = (const float*)d_in[11];
    const float* aS3 = (const float*)d_in[12];
    const float* aD3 = (const float*)d_in[13];
    const float* b3  = (const float*)d_in[14];

    const int E = in_sizes[2];
    const int n = NN;

    // lazily-created side stream + fork/join events (first call is the
    // uncaptured correctness run, so creation never happens during capture)
    static cudaStream_t s1 = nullptr;
    static cudaEvent_t evFork = nullptr, evJoin = nullptr;
    if (!s1) {
        cudaStreamCreateWithFlags(&s1, cudaStreamNonBlocking);
        cudaEventCreateWithFlags(&evFork, cudaEventDisableTiming);
        cudaEventCreateWithFlags(&evJoin, cudaEventDisableTiming);
    }
    cudaStream_t s0 = 0;   // capture (legacy) stream

    const int nodeBlocks = (n + 3) / 4;
    dim3 gemmGrid2(D1 / 64, (n + 127) / 128);
    dim3 gemmGrid1(OUT_F / 64, (n + 127) / 128);

    // Fork: layer-1 GEMM on s1, concurrent with CSR build on s0.
    cudaEventRecord(evFork, s0);
    cudaStreamWaitEvent(s1, evFork, 0);
    k_gemm_tf32<<<gemmGrid2, 256, 0, s1>>>(x, W1, n, IN_F, D1);

    k_detect_zero<<<(n + 255) / 256, 256, 0, s0>>>(ei, E, n);
    k_count_deg<<<(E + 255) / 256, 256, 0, s0>>>(ei, E, n);
    k_scan1<<<NBLK, SCAN_B, 0, s0>>>(n);
    k_scan2<<<1, 64, 0, s0>>>();
    k_scan3<<<(n + 255) / 256, 256, 0, s0>>>(n);
    k_scatter<<<(E + 255) / 256, 256, 0, s0>>>(ei, ew, E, n);

    // Join: dots needs g_h (s1) and g_mxals init (s0/scan2).
    cudaEventRecord(evJoin, s1);
    cudaStreamWaitEvent(s0, evJoin, 0);

    // Layer 1: 256 -> 128, H=4, C=32, relu
    k_dots<4, 32, 0><<<nodeBlocks, 128, 0, s0>>>(aS1, aD1, n);
    k_aggregate<4, 32, true, 0><<<nodeBlocks, 128, 0, s0>>>(b1, nullptr, n);

    // Layer 2: 128 -> 128, H=4, C=32, relu
    k_gemm_tf32<<<gemmGrid2, 256, 0, s0>>>(nullptr, W2, n, D1, D1);
    k_dots<4, 32, 1><<<nodeBlocks, 128, 0, s0>>>(aS2, aD2, n);
    k_aggregate<4, 32, true, 1><<<nodeBlocks, 128, 0, s0>>>(b2, nullptr, n);

    // Layer 3: 128 -> 64, H=1, C=64, no relu
    k_gemm_tf32<<<gemmGrid1, 256, 0, s0>>>(nullptr, W3, n, D1, OUT_F);
    k_dots<1, 64, 2><<<nodeBlocks, 128, 0, s0>>>(aS3, aD3, n);
    k_aggregate<1, 64, false, 2><<<nodeBlocks, 128, 0, s0>>>(b3, (float*)d_out, n);
}

// round 15
// speedup vs baseline: 1.1345x; 1.0302x over previous
#include <cuda_runtime.h>
#include <cuda_fp16.h>
#include <math.h>

// Problem constants (match reference)
#define NN 50000
#define NE 800000
#define IN_F 256
#define D1 128      // HEADS*HID
#define OUT_F 64
#define SLOPE 0.2f

#define SCAN_B 1024
#define NBLK ((NN + SCAN_B - 1) / SCAN_B)   // 49

// ---------------- device scratch (no allocations allowed) ----------------
__device__ __align__(16) __half g_h[(size_t)NN * D1];    // GEMM output, fp16 (gather path)
__device__ __align__(16) float  g_act[(size_t)NN * D1];  // post-aggregate activations, fp32
__device__ __align__(16) float  g_als[(size_t)NN * 4];
__device__ __align__(16) float  g_ald[(size_t)NN * 4];
__device__ int   g_rowptr[NN + 1];
__device__ int   g_deg[NN];
__device__ int   g_cursor[NN];
__device__ __align__(8) int2 g_csr[NE];    // (src, weight-bits) packed
__device__ int   g_bsum[NBLK];
__device__ int   g_boff[NBLK];
__device__ unsigned g_mxals[3][4];         // per-layer per-head global max(als), int-encoded
__device__ int   g_idx64;

// monotone float<->uint encoding for atomicMax on floats (0u acts as -inf)
__device__ __forceinline__ unsigned fenc(float f) {
    int b = __float_as_int(f);
    return (b >= 0) ? ((unsigned)b | 0x80000000u) : ~(unsigned)b;
}
__device__ __forceinline__ float fdec(unsigned u) {
    int b = (u & 0x80000000u) ? (int)(u & 0x7fffffffu) : ~(int)u;
    return __int_as_float(b);
}

// ---------------- fused: zero deg + dtype detect (block 0) ----------------
__global__ void k_detect_zero(const void* ei_raw, int E, int n) {
    int i = blockIdx.x * blockDim.x + threadIdx.x;
    if (i < n) g_deg[i] = 0;
    if (blockIdx.x == 0) {
        __shared__ int ok;
        if (threadIdx.x == 0) ok = 1;
        __syncthreads();
        const long long* p = (const long long*)ei_raw;
        int nchk = 2 * E < 256 ? 2 * E : 256;
        if (threadIdx.x < nchk) {
            long long v = p[threadIdx.x];
            if (v < 0 || v >= NN) atomicAnd(&ok, 0);
        }
        __syncthreads();
        if (threadIdx.x == 0) g_idx64 = ok;
    }
}

__device__ __forceinline__ void load_edge(const void* ei_raw, int E, int e, int idx64,
                                          int& s, int& d) {
    if (idx64) {
        const long long* p = (const long long*)ei_raw;
        s = (int)p[e];
        d = (int)p[E + e];
    } else {
        const int* p = (const int*)ei_raw;
        s = p[e];
        d = p[E + e];
    }
}

// ---------------- CSR construction ----------------
__global__ void k_count_deg(const void* ei_raw, int E, int n) {
    int e = blockIdx.x * blockDim.x + threadIdx.x;
    int idx64 = g_idx64;
    if (e < E) {
        int s, d;
        load_edge(ei_raw, E, e, idx64, s, d);
        if (d >= 0 && d < n) atomicAdd(&g_deg[d], 1);
    }
}

__global__ void k_scan1(int n) {
    int t = threadIdx.x;
    int i = blockIdx.x * SCAN_B + t;
    int lane = t & 31, w = t >> 5;
    int v = (i < n) ? g_deg[i] : 0;
    int x = v;
#pragma unroll
    for (int o = 1; o < 32; o <<= 1) {
        int y = __shfl_up_sync(0xffffffffu, x, o);
        if (lane >= o) x += y;
    }
    __shared__ int ws[32];
    if (lane == 31) ws[w] = x;
    __syncthreads();
    if (w == 0) {
        int y = ws[lane];
#pragma unroll
        for (int o = 1; o < 32; o <<= 1) {
            int z = __shfl_up_sync(0xffffffffu, y, o);
            if (lane >= o) y += z;
        }
        ws[lane] = y;
    }
    __syncthreads();
    int incl = x + (w > 0 ? ws[w - 1] : 0);
    if (i < n) g_rowptr[i + 1] = incl;
    if (t == SCAN_B - 1) g_bsum[blockIdx.x] = incl;
}

__global__ void k_scan2() {
    int t = threadIdx.x;
    int lane = t & 31, w = t >> 5;
    if (t < 12) ((unsigned*)g_mxals)[t] = 0u;    // init per-layer max slots
    int v = (t < NBLK) ? g_bsum[t] : 0;
    int x = v;
#pragma unroll
    for (int o = 1; o < 32; o <<= 1) {
        int y = __shfl_up_sync(0xffffffffu, x, o);
        if (lane >= o) x += y;
    }
    __shared__ int ws[2];
    if (lane == 31) ws[w] = x;
    __syncthreads();
    int incl = x + (w > 0 ? ws[0] : 0);
    if (t < NBLK) g_boff[t] = incl - v;
}

__global__ void k_scan3(int n) {
    int i = blockIdx.x * blockDim.x + threadIdx.x;
    if (i < n) {
        int incl = g_rowptr[i + 1] + g_boff[i >> 10];
        g_rowptr[i + 1] = incl;
        g_cursor[i] = incl - g_deg[i];
        if (i == 0) g_rowptr[0] = 0;
    }
}

__global__ void k_scatter(const void* ei_raw, const float* __restrict__ ew, int E, int n) {
    int e = blockIdx.x * blockDim.x + threadIdx.x;
    int idx64 = g_idx64;
    if (e < E) {
        int s, d;
        load_edge(ei_raw, E, e, idx64, s, d);
        if (s >= 0 && s < n && d >= 0 && d < n) {
            int pos = atomicAdd(&g_cursor[d], 1);
            if (pos >= 0 && pos < E) {
                g_csr[pos] = make_int2(s, __float_as_int(ew[e]));
            }
        }
    }
}

// ---------------- FP16 GEMM with ldmatrix (m16n8k16, fp32 accum) ----------------
// g_h[M,Nc] (fp16) = A[M,K] @ B[K,Nc]. BM=128, BN=64, BK=32, 8 warps (4x2),
// warp tile 32x32. As [m][k] pitch 40 halves, Bs [k][n] pitch 72 halves —
// both verified conflict-free for ldmatrix phases and uint4 STS.
#define LDSM_X4(r0, r1, r2, r3, addr) \
    asm volatile("ldmatrix.sync.aligned.m8n8.x4.shared.b16 {%0,%1,%2,%3}, [%4];" \
                 : "=r"(r0), "=r"(r1), "=r"(r2), "=r"(r3) : "r"(addr))
#define LDSM_X4T(r0, r1, r2, r3, addr) \
    asm volatile("ldmatrix.sync.aligned.m8n8.x4.trans.shared.b16 {%0,%1,%2,%3}, [%4];" \
                 : "=r"(r0), "=r"(r1), "=r"(r2), "=r"(r3) : "r"(addr))

__global__ __launch_bounds__(256)
void k_gemm_f16(const float* __restrict__ Aext, const float* __restrict__ B,
                int M, int K, int Nc) {
    constexpr int BM = 128, BN = 64, BK = 32;
    constexpr int AP = 40;   // As pitch (halves); 80B rows -> 16B-aligned, cf-free
    constexpr int BP = 72;   // Bs pitch (halves); 144B rows -> 16B-aligned, cf-free
    __shared__ __align__(16) __half As[BM][AP];   // [m][k]
    __shared__ __align__(16) __half Bs[BK][BP];   // [k][n]

    const float* __restrict__ A = Aext ? Aext : g_act;
    __half* __restrict__ C = g_h;

    int tid = threadIdx.x;
    int lane = tid & 31;
    int warp = tid >> 5;
    int wm = warp >> 1;          // 0..3 -> m offset 32*wm
    int wn = warp & 1;           // 0..1 -> n offset 32*wn
    int bm0 = blockIdx.y * BM;
    int bn0 = blockIdx.x * BN;

    float acc[2][4][4];
#pragma unroll
    for (int mt = 0; mt < 2; mt++)
#pragma unroll
        for (int nt = 0; nt < 4; nt++)
#pragma unroll
            for (int i = 0; i < 4; i++) acc[mt][nt][i] = 0.f;

    // A loader: 2 threads/row, 16 floats each -> 16 halves (2 uint4 STS)
    int arow = tid >> 1;
    int acol0 = (tid & 1) * 16;
    int grow = bm0 + arow;
    // B loader: thread t: k row = t>>3, 8 n at (t&7)*8 (row-major, NO transpose)
    int kb = tid >> 3;
    int nb0 = (tid & 7) * 8;

    unsigned asbase = (unsigned)__cvta_generic_to_shared(&As[0][0]);
    unsigned bsbase = (unsigned)__cvta_generic_to_shared(&Bs[0][0]);

    for (int k0 = 0; k0 < K; k0 += BK) {
        {
            const float* ap = A + (size_t)grow * K + k0 + acol0;
            unsigned hw[8];
#pragma unroll
            for (int j = 0; j < 4; j++) {
                float4 v = (grow < M) ? *(const float4*)(ap + j * 4)
                                      : make_float4(0.f, 0.f, 0.f, 0.f);
                __half2 h01 = __floats2half2_rn(v.x, v.y);
                __half2 h23 = __floats2half2_rn(v.z, v.w);
                hw[j * 2 + 0] = *reinterpret_cast<unsigned*>(&h01);
                hw[j * 2 + 1] = *reinterpret_cast<unsigned*>(&h23);
            }
            uint4* dst = reinterpret_cast<uint4*>(&As[arow][acol0]);
            dst[0] = make_uint4(hw[0], hw[1], hw[2], hw[3]);
            dst[1] = make_uint4(hw[4], hw[5], hw[6], hw[7]);
        }
        {
            const float* bp = B + (size_t)(k0 + kb) * Nc + bn0 + nb0;
            float4 v0 = *(const float4*)bp;
            float4 v1 = *(const float4*)(bp + 4);
            __half2 h0 = __floats2half2_rn(v0.x, v0.y);
            __half2 h1 = __floats2half2_rn(v0.z, v0.w);
            __half2 h2 = __floats2half2_rn(v1.x, v1.y);
            __half2 h3 = __floats2half2_rn(v1.z, v1.w);
            *reinterpret_cast<uint4*>(&Bs[kb][nb0]) =
                make_uint4(*reinterpret_cast<unsigned*>(&h0),
                           *reinterpret_cast<unsigned*>(&h1),
                           *reinterpret_cast<unsigned*>(&h2),
                           *reinterpret_cast<unsigned*>(&h3));
        }
        __syncthreads();

#pragma unroll
        for (int kk = 0; kk < BK; kk += 16) {
            // A fragments: x4 mats (m0-7,k0-7)(m8-15,k0-7)(m0-7,k8-15)(m8-15,k8-15)
            unsigned afr[2][4];
#pragma unroll
            for (int mt = 0; mt < 2; mt++) {
                int row = wm * 32 + mt * 16 + (lane & 15);
                int col = kk + ((lane >> 4) << 3);
                unsigned addr = asbase + (unsigned)(row * AP + col) * 2u;
                LDSM_X4(afr[mt][0], afr[mt][1], afr[mt][2], afr[mt][3], addr);
            }
            // B fragments: x4.trans mats (k,n)(k+8,n)(k,n+8)(k+8,n+8)
            unsigned bfr[4][2];
#pragma unroll
            for (int np = 0; np < 2; np++) {
                int krow = kk + (lane & 15);
                int ncol = wn * 32 + np * 16 + ((lane >> 4) << 3);
                unsigned addr = bsbase + (unsigned)(krow * BP + ncol) * 2u;
                unsigned r0, r1, r2, r3;
                LDSM_X4T(r0, r1, r2, r3, addr);
                bfr[np * 2 + 0][0] = r0; bfr[np * 2 + 0][1] = r1;
                bfr[np * 2 + 1][0] = r2; bfr[np * 2 + 1][1] = r3;
            }
#pragma unroll
            for (int mt = 0; mt < 2; mt++)
#pragma unroll
                for (int nt = 0; nt < 4; nt++) {
                    asm volatile(
                        "mma.sync.aligned.m16n8k16.row.col.f32.f16.f16.f32 "
                        "{%0,%1,%2,%3}, {%4,%5,%6,%7}, {%8,%9}, {%0,%1,%2,%3};"
                        : "+f"(acc[mt][nt][0]), "+f"(acc[mt][nt][1]),
                          "+f"(acc[mt][nt][2]), "+f"(acc[mt][nt][3])
                        : "r"(afr[mt][0]), "r"(afr[mt][1]), "r"(afr[mt][2]), "r"(afr[mt][3]),
                          "r"(bfr[nt][0]), "r"(bfr[nt][1]));
                }
        }
        __syncthreads();
    }

    // epilogue: fp32 acc -> fp16 stores (c-fragment layout: m16n8)
#pragma unroll
    for (int mt = 0; mt < 2; mt++) {
        int r = bm0 + wm * 32 + mt * 16 + (lane >> 2);
#pragma unroll
        for (int nt = 0; nt < 4; nt++) {
            int c = bn0 + wn * 32 + nt * 8 + (lane & 3) * 2;
            if (r < M) {
                __half2 v0 = __floats2half2_rn(acc[mt][nt][0], acc[mt][nt][1]);
                *(__half2*)(C + (size_t)r * Nc + c) = v0;
            }
            if (r + 8 < M) {
                __half2 v1 = __floats2half2_rn(acc[mt][nt][2], acc[mt][nt][3]);
                *(__half2*)(C + (size_t)(r + 8) * Nc + c) = v1;
            }
        }
    }
}

// ---------------- dots + fused global max ----------------
template <int H, int C, int LAYER>
__global__ void k_dots(const float* __restrict__ a_src, const float* __restrict__ a_dst, int n) {
    constexpr int D = H * C;
    constexpr int CPL = D / 32;
    constexpr int G = 32 / H;
    int wid = threadIdx.x >> 5;
    int lane = threadIdx.x & 31;
    int node = blockIdx.x * 4 + wid;
    bool valid = node < n;

    float ss = 0.f, sd = 0.f;
    int c0 = lane * CPL;
    if (valid) {
        float hv[CPL];
        const __half* hr = g_h + (size_t)node * D + c0;
        if (CPL == 4) {
            uint2 raw = *(const uint2*)hr;
            float2 f01 = __half22float2(*reinterpret_cast<__half2*>(&raw.x));
            float2 f23 = __half22float2(*reinterpret_cast<__half2*>(&raw.y));
            hv[0] = f01.x; hv[1] = f01.y; hv[2] = f23.x; hv[3] = f23.y;
        } else {
            unsigned raw = *(const unsigned*)hr;
            float2 f01 = __half22float2(*reinterpret_cast<__half2*>(&raw));
            hv[0] = f01.x; hv[1] = f01.y;
        }
#pragma unroll
        for (int j = 0; j < CPL; j++) {
            ss = fmaf(hv[j], a_src[c0 + j], ss);
            sd = fmaf(hv[j], a_dst[c0 + j], sd);
        }
    }
#pragma unroll
    for (int o = G / 2; o > 0; o >>= 1) {
        ss += __shfl_down_sync(0xffffffffu, ss, o, G);
        sd += __shfl_down_sync(0xffffffffu, sd, o, G);
    }
    __shared__ float smax[4][H];
    if ((lane % G) == 0) {
        int hd = lane / G;
        if (valid) {
            g_als[(size_t)node * H + hd] = ss;
            g_ald[(size_t)node * H + hd] = sd;
        }
        smax[wid][hd] = valid ? ss : -1e30f;
    }
    __syncthreads();
    if (threadIdx.x < H) {
        float m = smax[0][threadIdx.x];
#pragma unroll
        for (int ww = 1; ww < 4; ww++) m = fmaxf(m, smax[ww][threadIdx.x]);
        atomicMax(&g_mxals[LAYER][threadIdx.x], fenc(m));
    }
}

// ---------------- fused segment softmax + weighted aggregate (unrolled x4) ----------------
template <int H, int C, bool RELU, int LAYER>
__global__ void k_aggregate(const float* __restrict__ bias, float* __restrict__ outExt, int n) {
    constexpr int D = H * C;
    constexpr int CPL = D / 32;
    constexpr int G = 32 / H;
    float* __restrict__ out = outExt ? outExt : g_act;
    int wid = threadIdx.x >> 5;
    int lane = threadIdx.x & 31;
    int node = blockIdx.x * 4 + wid;
    if (node >= n) return;

    int s0 = g_rowptr[node];
    int s1 = g_rowptr[node + 1];

    int c0 = lane * CPL;
    int hd = lane / G;
    float myald = g_ald[(size_t)node * H + hd];
    float Mh = fdec(g_mxals[LAYER][hd]);
    float mymx = Mh + myald;
    mymx = (mymx > 0.f) ? mymx : SLOPE * mymx;

    float acc[CPL];
#pragma unroll
    for (int j = 0; j < CPL; j++) acc[j] = 0.f;
    float esum = 0.f;

    int i = s0;
    for (; i + 4 <= s1; i += 4) {
        int2 p0 = g_csr[i + 0];
        int2 p1 = g_csr[i + 1];
        int2 p2 = g_csr[i + 2];
        int2 p3 = g_csr[i + 3];
        float a0 = g_als[(size_t)p0.x * H + hd];
        float a1 = g_als[(size_t)p1.x * H + hd];
        float a2 = g_als[(size_t)p2.x * H + hd];
        float a3 = g_als[(size_t)p3.x * H + hd];
        if (CPL == 4) {
            uint2 r0 = *(const uint2*)(g_h + (size_t)p0.x * D + c0);
            uint2 r1 = *(const uint2*)(g_h + (size_t)p1.x * D + c0);
            uint2 r2 = *(const uint2*)(g_h + (size_t)p2.x * D + c0);
            uint2 r3 = *(const uint2*)(g_h + (size_t)p3.x * D + c0);
            float l0 = a0 + myald; l0 = (l0 > 0.f) ? l0 : SLOPE * l0;
            float l1 = a1 + myald; l1 = (l1 > 0.f) ? l1 : SLOPE * l1;
            float l2 = a2 + myald; l2 = (l2 > 0.f) ? l2 : SLOPE * l2;
            float l3 = a3 + myald; l3 = (l3 > 0.f) ? l3 : SLOPE * l3;
            float e0 = __expf(l0 - mymx) * __int_as_float(p0.y);
            float e1 = __expf(l1 - mymx) * __int_as_float(p1.y);
            float e2 = __expf(l2 - mymx) * __int_as_float(p2.y);
            float e3 = __expf(l3 - mymx) * __int_as_float(p3.y);
            esum += (e0 + e1) + (e2 + e3);
            float2 f;
            f = __half22float2(*reinterpret_cast<__half2*>(&r0.x));
            acc[0] = fmaf(e0, f.x, acc[0]); acc[1] = fmaf(e0, f.y, acc[1]);
            f = __half22float2(*reinterpret_cast<__half2*>(&r0.y));
            acc[2] = fmaf(e0, f.x, acc[2]); acc[3] = fmaf(e0, f.y, acc[3]);
            f = __half22float2(*reinterpret_cast<__half2*>(&r1.x));
            acc[0] = fmaf(e1, f.x, acc[0]); acc[1] = fmaf(e1, f.y, acc[1]);
            f = __half22float2(*reinterpret_cast<__half2*>(&r1.y));
            acc[2] = fmaf(e1, f.x, acc[2]); acc[3] = fmaf(e1, f.y, acc[3]);
            f = __half22float2(*reinterpret_cast<__half2*>(&r2.x));
            acc[0] = fmaf(e2, f.x, acc[0]); acc[1] = fmaf(e2, f.y, acc[1]);
            f = __half22float2(*reinterpret_cast<__half2*>(&r2.y));
            acc[2] = fmaf(e2, f.x, acc[2]); acc[3] = fmaf(e2, f.y, acc[3]);
            f = __half22float2(*reinterpret_cast<__half2*>(&r3.x));
            acc[0] = fmaf(e3, f.x, acc[0]); acc[1] = fmaf(e3, f.y, acc[1]);
            f = __half22float2(*reinterpret_cast<__half2*>(&r3.y));
            acc[2] = fmaf(e3, f.x, acc[2]); acc[3] = fmaf(e3, f.y, acc[3]);
        } else {
            unsigned r0 = *(const unsigned*)(g_h + (size_t)p0.x * D + c0);
            unsigned r1 = *(const unsigned*)(g_h + (size_t)p1.x * D + c0);
            unsigned r2 = *(const unsigned*)(g_h + (size_t)p2.x * D + c0);
            unsigned r3 = *(const unsigned*)(g_h + (size_t)p3.x * D + c0);
            float l0 = a0 + myald; l0 = (l0 > 0.f) ? l0 : SLOPE * l0;
            float l1 = a1 + myald; l1 = (l1 > 0.f) ? l1 : SLOPE * l1;
            float l2 = a2 + myald; l2 = (l2 > 0.f) ? l2 : SLOPE * l2;
            float l3 = a3 + myald; l3 = (l3 > 0.f) ? l3 : SLOPE * l3;
            float e0 = __expf(l0 - mymx) * __int_as_float(p0.y);
            float e1 = __expf(l1 - mymx) * __int_as_float(p1.y);
            float e2 = __expf(l2 - mymx) * __int_as_float(p2.y);
            float e3 = __expf(l3 - mymx) * __int_as_float(p3.y);
            esum += (e0 + e1) + (e2 + e3);
            float2 f;
            f = __half22float2(*reinterpret_cast<__half2*>(&r0));
            acc[0] = fmaf(e0, f.x, acc[0]); acc[1] = fmaf(e0, f.y, acc[1]);
            f = __half22float2(*reinterpret_cast<__half2*>(&r1));
            acc[0] = fmaf(e1, f.x, acc[0]); acc[1] = fmaf(e1, f.y, acc[1]);
            f = __half22float2(*reinterpret_cast<__half2*>(&r2));
            acc[0] = fmaf(e2, f.x, acc[0]); acc[1] = fmaf(e2, f.y, acc[1]);
            f = __half22float2(*reinterpret_cast<__half2*>(&r3));
            acc[0] = fmaf(e3, f.x, acc[0]); acc[1] = fmaf(e3, f.y, acc[1]);
        }
    }
    for (; i < s1; i++) {
        int2 p = g_csr[i];
        float l = g_als[(size_t)p.x * H + hd] + myald;
        l = (l > 0.f) ? l : SLOPE * l;
        float e = __expf(l - mymx) * __int_as_float(p.y);
        esum += e;
        const __half* hp = g_h + (size_t)p.x * D + c0;
        if (CPL == 4) {
            uint2 raw = *(const uint2*)hp;
            float2 f01 = __half22float2(*reinterpret_cast<__half2*>(&raw.x));
            float2 f23 = __half22float2(*reinterpret_cast<__half2*>(&raw.y));
            acc[0] = fmaf(e, f01.x, acc[0]);
            acc[1] = fmaf(e, f01.y, acc[1]);
            acc[2] = fmaf(e, f23.x, acc[2]);
            acc[3] = fmaf(e, f23.y, acc[3]);
        } else {
            unsigned raw = *(const unsigned*)hp;
            float2 f01 = __half22float2(*reinterpret_cast<__half2*>(&raw));
            acc[0] = fmaf(e, f01.x, acc[0]);
            acc[1] = fmaf(e, f01.y, acc[1]);
        }
    }
    float inv = 1.0f / (esum + 1e-16f);
#pragma unroll
    for (int j = 0; j < CPL; j++) {
        float v = fmaf(acc[j], inv, bias[c0 + j]);
        if (RELU) v = fmaxf(v, 0.f);
        out[(size_t)node * D + c0 + j] = v;
    }
}

// ---------------- host launch ----------------
extern "C" void kernel_launch(void* const* d_in, const int* in_sizes, int n_in,
                              void* d_out, int out_size) {
    const float* x   = (const float*)d_in[0];
    const void*  ei  = d_in[1];
    const float* ew  = (const float*)d_in[2];
    const float* W1  = (const float*)d_in[3];
    const float* aS1 = (const float*)d_in[4];
    const float* aD1 = (const float*)d_in[5];
    const float* b1  = (const float*)d_in[6];
    const float* W2  = (const float*)d_in[7];
    const float* aS2 = (const float*)d_in[8];
    const float* aD2 = (const float*)d_in[9];
    const float* b2  = (const float*)d_in[10];
    const float* W3  = (const float*)d_in[11];
    const float* aS3 = (const float*)d_in[12];
    const float* aD3 = (const float*)d_in[13];
    const float* b3  = (const float*)d_in[14];

    const int E = in_sizes[2];
    const int n = NN;

    // lazily-created side stream + fork/join events (first call is the
    // uncaptured correctness run, so creation never happens during capture)
    static cudaStream_t s1 = nullptr;
    static cudaEvent_t evFork = nullptr, evJoin = nullptr;
    if (!s1) {
        cudaStreamCreateWithFlags(&s1, cudaStreamNonBlocking);
        cudaEventCreateWithFlags(&evFork, cudaEventDisableTiming);
        cudaEventCreateWithFlags(&evJoin, cudaEventDisableTiming);
    }
    cudaStream_t s0 = 0;   // capture (legacy) stream

    const int nodeBlocks = (n + 3) / 4;
    dim3 gemmGrid2(D1 / 64, (n + 127) / 128);
    dim3 gemmGrid1(OUT_F / 64, (n + 127) / 128);

    // Fork: layer-1 GEMM on s1, concurrent with CSR build on s0.
    cudaEventRecord(evFork, s0);
    cudaStreamWaitEvent(s1, evFork, 0);
    k_gemm_f16<<<gemmGrid2, 256, 0, s1>>>(x, W1, n, IN_F, D1);

    k_detect_zero<<<(n + 255) / 256, 256, 0, s0>>>(ei, E, n);
    k_count_deg<<<(E + 255) / 256, 256, 0, s0>>>(ei, E, n);
    k_scan1<<<NBLK, SCAN_B, 0, s0>>>(n);
    k_scan2<<<1, 64, 0, s0>>>();
    k_scan3<<<(n + 255) / 256, 256, 0, s0>>>(n);
    k_scatter<<<(E + 255) / 256, 256, 0, s0>>>(ei, ew, E, n);

    // Join: dots needs g_h (s1) and g_mxals init (s0/scan2).
    cudaEventRecord(evJoin, s1);
    cudaStreamWaitEvent(s0, evJoin, 0);

    // Layer 1: 256 -> 128, H=4, C=32, relu
    k_dots<4, 32, 0><<<nodeBlocks, 128, 0, s0>>>(aS1, aD1, n);
    k_aggregate<4, 32, true, 0><<<nodeBlocks, 128, 0, s0>>>(b1, nullptr, n);

    // Layer 2: 128 -> 128, H=4, C=32, relu
    k_gemm_f16<<<gemmGrid2, 256, 0, s0>>>(nullptr, W2, n, D1, D1);
    k_dots<4, 32, 1><<<nodeBlocks, 128, 0, s0>>>(aS2, aD2, n);
    k_aggregate<4, 32, true, 1><<<nodeBlocks, 128, 0, s0>>>(b2, nullptr, n);

    // Layer 3: 128 -> 64, H=1, C=64, no relu
    k_gemm_f16<<<gemmGrid1, 256, 0, s0>>>(nullptr, W3, n, D1, OUT_F);
    k_dots<1, 64, 2><<<nodeBlocks, 128, 0, s0>>>(aS3, aD3, n);
    k_aggregate<1, 64, false, 2><<<nodeBlocks, 128, 0, s0>>>(b3, (float*)d_out, n);
}

// round 16
// speedup vs baseline: 1.1896x; 1.0486x over previous
#include <cuda_runtime.h>
#include <cuda_fp16.h>
#include <math.h>

#define NN 50000
#define NE 800000
#define IN_F 256
#define D1 128
#define OUT_F 64
#define SLOPE 0.2f

#define SCAN_B 1024
#define NBLK ((NN + SCAN_B - 1) / SCAN_B)

__device__ __align__(16) __half g_h[(size_t)NN * D1];
__device__ __align__(16) __half g_acth[(size_t)NN * D1];
__device__ __align__(16) __half g_xh[(size_t)NN * IN_F];
__device__ __align__(16) float  g_als[(size_t)NN * 4];
__device__ __align__(16) float  g_ald[(size_t)NN * 4];
__device__ int   g_rowptr[NN + 1];
__device__ int   g_deg[NN];
__device__ int   g_cursor[NN];
__device__ __align__(8) int2 g_csr[NE];
__device__ int   g_bsum[NBLK];
__device__ int   g_boff[NBLK];
__device__ unsigned g_mxals[3][4];
__device__ int   g_idx64;

__device__ __forceinline__ unsigned fenc(float f) {
    int b = __float_as_int(f);
    return (b >= 0) ? ((unsigned)b | 0x80000000u) : ~(unsigned)b;
}
__device__ __forceinline__ float fdec(unsigned u) {
    int b = (u & 0x80000000u) ? (int)(u & 0x7fffffffu) : ~(int)u;
    return __int_as_float(b);
}

__global__ void k_x2h(const float* __restrict__ x, int total8) {
    int i = blockIdx.x * blockDim.x + threadIdx.x;
    if (i < total8) {
        const float4* src = (const float4*)(x + (size_t)i * 8);
        float4 v0 = src[0], v1 = src[1];
        __half2 h0 = __floats2half2_rn(v0.x, v0.y);
        __half2 h1 = __floats2half2_rn(v0.z, v0.w);
        __half2 h2 = __floats2half2_rn(v1.x, v1.y);
        __half2 h3 = __floats2half2_rn(v1.z, v1.w);
        *reinterpret_cast<uint4*>(g_xh + (size_t)i * 8) =
            make_uint4(*reinterpret_cast<unsigned*>(&h0), *reinterpret_cast<unsigned*>(&h1),
                       *reinterpret_cast<unsigned*>(&h2), *reinterpret_cast<unsigned*>(&h3));
    }
}

__global__ void k_detect_zero(const void* ei_raw, int E, int n) {
    int i = blockIdx.x * blockDim.x + threadIdx.x;
    if (i < n) g_deg[i] = 0;
    if (blockIdx.x == 0) {
        __shared__ int ok;
        if (threadIdx.x == 0) ok = 1;
        __syncthreads();
        const long long* p = (const long long*)ei_raw;
        int nchk = 2 * E < 256 ? 2 * E : 256;
        if (threadIdx.x < nchk) {
            long long v = p[threadIdx.x];
            if (v < 0 || v >= NN) atomicAnd(&ok, 0);
        }
        __syncthreads();
        if (threadIdx.x == 0) g_idx64 = ok;
    }
}

__device__ __forceinline__ void load_edge(const void* ei_raw, int E, int e, int idx64,
                                          int& s, int& d) {
    if (idx64) {
        const long long* p = (const long long*)ei_raw;
        s = (int)p[e]; d = (int)p[E + e];
    } else {
        const int* p = (const int*)ei_raw;
        s = p[e]; d = p[E + e];
    }
}

__global__ void k_count_deg(const void* ei_raw, int E, int n) {
    int e = blockIdx.x * blockDim.x + threadIdx.x;
    int idx64 = g_idx64;
    if (e < E) {
        int s, d;
        load_edge(ei_raw, E, e, idx64, s, d);
        if (d >= 0 && d < n) atomicAdd(&g_deg[d], 1);
    }
}

__global__ void k_scan1(int n) {
    int t = threadIdx.x;
    int i = blockIdx.x * SCAN_B + t;
    int lane = t & 31, w = t >> 5;
    int v = (i < n) ? g_deg[i] : 0;
    int x = v;
#pragma unroll
    for (int o = 1; o < 32; o <<= 1) {
        int y = __shfl_up_sync(0xffffffffu, x, o);
        if (lane >= o) x += y;
    }
    __shared__ int ws[32];
    if (lane == 31) ws[w] = x;
    __syncthreads();
    if (w == 0) {
        int y = ws[lane];
#pragma unroll
        for (int o = 1; o < 32; o <<= 1) {
            int z = __shfl_up_sync(0xffffffffu, y, o);
            if (lane >= o) y += z;
        }
        ws[lane] = y;
    }
    __syncthreads();
    int incl = x + (w > 0 ? ws[w - 1] : 0);
    if (i < n) g_rowptr[i + 1] = incl;
    if (t == SCAN_B - 1) g_bsum[blockIdx.x] = incl;
}

__global__ void k_scan2() {
    int t = threadIdx.x;
    int lane = t & 31, w = t >> 5;
    if (t < 12) ((unsigned*)g_mxals)[t] = 0u;
    int v = (t < NBLK) ? g_bsum[t] : 0;
    int x = v;
#pragma unroll
    for (int o = 1; o < 32; o <<= 1) {
        int y = __shfl_up_sync(0xffffffffu, x, o);
        if (lane >= o) x += y;
    }
    __shared__ int ws[2];
    if (lane == 31) ws[w] = x;
    __syncthreads();
    int incl = x + (w > 0 ? ws[0] : 0);
    if (t < NBLK) g_boff[t] = incl - v;
}

__global__ void k_scan3(int n) {
    int i = blockIdx.x * blockDim.x + threadIdx.x;
    if (i < n) {
        int incl = g_rowptr[i + 1] + g_boff[i >> 10];
        g_rowptr[i + 1] = incl;
        g_cursor[i] = incl - g_deg[i];
        if (i == 0) g_rowptr[0] = 0;
    }
}

__global__ void k_scatter(const void* ei_raw, const float* __restrict__ ew, int E, int n) {
    int e = blockIdx.x * blockDim.x + threadIdx.x;
    int idx64 = g_idx64;
    if (e < E) {
        int s, d;
        load_edge(ei_raw, E, e, idx64, s, d);
        if (s >= 0 && s < n && d >= 0 && d < n) {
            int pos = atomicAdd(&g_cursor[d], 1);
            if (pos >= 0 && pos < E) g_csr[pos] = make_int2(s, __float_as_int(ew[e]));
        }
    }
}

#define LDSM_X4(r0, r1, r2, r3, addr) \
    asm volatile("ldmatrix.sync.aligned.m8n8.x4.shared.b16 {%0,%1,%2,%3}, [%4];" \
                 : "=r"(r0), "=r"(r1), "=r"(r2), "=r"(r3) : "r"(addr))
#define LDSM_X4T(r0, r1, r2, r3, addr) \
    asm volatile("ldmatrix.sync.aligned.m8n8.x4.trans.shared.b16 {%0,%1,%2,%3}, [%4];" \
                 : "=r"(r0), "=r"(r1), "=r"(r2), "=r"(r3) : "r"(addr))

// fp16-A GEMM with cp.async double-buffer. A selected by template (0=g_xh, 1=g_acth).
template <int ASRC>
__global__ __launch_bounds__(256)
void k_gemm_f16(const float* __restrict__ B, int M, int K, int Nc) {
    constexpr int BM = 128, BN = 64, BK = 32;
    constexpr int AP = 40, BP = 72;
    __shared__ __align__(16) __half As[2][BM][AP];
    __shared__ __align__(16) __half Bs[2][BK][BP];

    const __half* __restrict__ A = (ASRC == 0) ? g_xh : g_acth;
    __half* __restrict__ C = g_h;

    int tid = threadIdx.x;
    int lane = tid & 31;
    int warp = tid >> 5;
    int wm = warp >> 1;
    int wn = warp & 1;
    int bm0 = blockIdx.y * BM;
    int bn0 = blockIdx.x * BN;

    float acc[2][4][4];
#pragma unroll
    for (int mt = 0; mt < 2; mt++)
#pragma unroll
        for (int nt = 0; nt < 4; nt++)
#pragma unroll
            for (int i = 0; i < 4; i++) acc[mt][nt][i] = 0.f;

    int arow = tid >> 1;
    int acol0 = (tid & 1) * 16;
    int grow = bm0 + arow;
    int arowc = (grow < M) ? grow : 0;
    int asz = (grow < M) ? 16 : 0;
    int kb = tid >> 3;
    int nb0 = (tid & 7) * 8;

    const __half* abase = A + (size_t)arowc * K + acol0;

    int KT = K / BK;

    // prologue: stage 0
    {
        unsigned dst = (unsigned)__cvta_generic_to_shared(&As[0][arow][acol0]);
        asm volatile("cp.async.ca.shared.global [%0], [%1], 16, %2;" :: "r"(dst), "l"(abase), "r"(asz));
        asm volatile("cp.async.ca.shared.global [%0], [%1], 16, %2;" :: "r"(dst + 16), "l"(abase + 8), "r"(asz));
        asm volatile("cp.async.commit_group;");
        const float* bp = B + (size_t)kb * Nc + bn0 + nb0;
        float4 v0 = *(const float4*)bp;
        float4 v1 = *(const float4*)(bp + 4);
        __half2 h0 = __floats2half2_rn(v0.x, v0.y);
        __half2 h1 = __floats2half2_rn(v0.z, v0.w);
        __half2 h2 = __floats2half2_rn(v1.x, v1.y);
        __half2 h3 = __floats2half2_rn(v1.z, v1.w);
        *reinterpret_cast<uint4*>(&Bs[0][kb][nb0]) =
            make_uint4(*reinterpret_cast<unsigned*>(&h0), *reinterpret_cast<unsigned*>(&h1),
                       *reinterpret_cast<unsigned*>(&h2), *reinterpret_cast<unsigned*>(&h3));
        asm volatile("cp.async.wait_group 0;");
    }
    __syncthreads();

    for (int kt = 0; kt < KT; kt++) {
        int cur = kt & 1, nxt = cur ^ 1;
        if (kt + 1 < KT) {
            int k0 = (kt + 1) * BK;
            unsigned dst = (unsigned)__cvta_generic_to_shared(&As[nxt][arow][acol0]);
            const __half* src = abase + k0;
            asm volatile("cp.async.ca.shared.global [%0], [%1], 16, %2;" :: "r"(dst), "l"(src), "r"(asz));
            asm volatile("cp.async.ca.shared.global [%0], [%1], 16, %2;" :: "r"(dst + 16), "l"(src + 8), "r"(asz));
            asm volatile("cp.async.commit_group;");
            const float* bp = B + (size_t)(k0 + kb) * Nc + bn0 + nb0;
            float4 v0 = *(const float4*)bp;
            float4 v1 = *(const float4*)(bp + 4);
            __half2 h0 = __floats2half2_rn(v0.x, v0.y);
            __half2 h1 = __floats2half2_rn(v0.z, v0.w);
            __half2 h2 = __floats2half2_rn(v1.x, v1.y);
            __half2 h3 = __floats2half2_rn(v1.z, v1.w);
            *reinterpret_cast<uint4*>(&Bs[nxt][kb][nb0]) =
                make_uint4(*reinterpret_cast<unsigned*>(&h0), *reinterpret_cast<unsigned*>(&h1),
                           *reinterpret_cast<unsigned*>(&h2), *reinterpret_cast<unsigned*>(&h3));
        }

        unsigned asb = (unsigned)__cvta_generic_to_shared(&As[cur][0][0]);
        unsigned bsb = (unsigned)__cvta_generic_to_shared(&Bs[cur][0][0]);
#pragma unroll
        for (int kk = 0; kk < BK; kk += 16) {
            unsigned afr[2][4];
#pragma unroll
            for (int mt = 0; mt < 2; mt++) {
                int row = wm * 32 + mt * 16 + (lane & 15);
                int col = kk + ((lane >> 4) << 3);
                unsigned addr = asb + (unsigned)(row * AP + col) * 2u;
                LDSM_X4(afr[mt][0], afr[mt][1], afr[mt][2], afr[mt][3], addr);
            }
            unsigned bfr[4][2];
#pragma unroll
            for (int np = 0; np < 2; np++) {
                int krow = kk + (lane & 15);
                int ncol = wn * 32 + np * 16 + ((lane >> 4) << 3);
                unsigned addr = bsb + (unsigned)(krow * BP + ncol) * 2u;
                unsigned r0, r1, r2, r3;
                LDSM_X4T(r0, r1, r2, r3, addr);
                bfr[np * 2 + 0][0] = r0; bfr[np * 2 + 0][1] = r1;
                bfr[np * 2 + 1][0] = r2; bfr[np * 2 + 1][1] = r3;
            }
#pragma unroll
            for (int mt = 0; mt < 2; mt++)
#pragma unroll
                for (int nt = 0; nt < 4; nt++) {
                    asm volatile(
                        "mma.sync.aligned.m16n8k16.row.col.f32.f16.f16.f32 "
                        "{%0,%1,%2,%3}, {%4,%5,%6,%7}, {%8,%9}, {%0,%1,%2,%3};"
                        : "+f"(acc[mt][nt][0]), "+f"(acc[mt][nt][1]),
                          "+f"(acc[mt][nt][2]), "+f"(acc[mt][nt][3])
                        : "r"(afr[mt][0]), "r"(afr[mt][1]), "r"(afr[mt][2]), "r"(afr[mt][3]),
                          "r"(bfr[nt][0]), "r"(bfr[nt][1]));
                }
        }
        if (kt + 1 < KT) asm volatile("cp.async.wait_group 0;");
        __syncthreads();
    }

#pragma unroll
    for (int mt = 0; mt < 2; mt++) {
        int r = bm0 + wm * 32 + mt * 16 + (lane >> 2);
#pragma unroll
        for (int nt = 0; nt < 4; nt++) {
            int c = bn0 + wn * 32 + nt * 8 + (lane & 3) * 2;
            if (r < M) {
                __half2 v0 = __floats2half2_rn(acc[mt][nt][0], acc[mt][nt][1]);
                *(__half2*)(C + (size_t)r * Nc + c) = v0;
            }
            if (r + 8 < M) {
                __half2 v1 = __floats2half2_rn(acc[mt][nt][2], acc[mt][nt][3]);
                *(__half2*)(C + (size_t)(r + 8) * Nc + c) = v1;
            }
        }
    }
}

template <int H, int C, int LAYER>
__global__ void k_dots(const float* __restrict__ a_src, const float* __restrict__ a_dst, int n) {
    constexpr int D = H * C;
    constexpr int CPL = D / 32;
    constexpr int G = 32 / H;
    int wid = threadIdx.x >> 5;
    int lane = threadIdx.x & 31;
    int node = blockIdx.x * 4 + wid;
    bool valid = node < n;

    float ss = 0.f, sd = 0.f;
    int c0 = lane * CPL;
    if (valid) {
        float hv[CPL];
        const __half* hr = g_h + (size_t)node * D + c0;
        if (CPL == 4) {
            uint2 raw = *(const uint2*)hr;
            float2 f01 = __half22float2(*reinterpret_cast<__half2*>(&raw.x));
            float2 f23 = __half22float2(*reinterpret_cast<__half2*>(&raw.y));
            hv[0] = f01.x; hv[1] = f01.y; hv[2] = f23.x; hv[3] = f23.y;
        } else {
            unsigned raw = *(const unsigned*)hr;
            float2 f01 = __half22float2(*reinterpret_cast<__half2*>(&raw));
            hv[0] = f01.x; hv[1] = f01.y;
        }
#pragma unroll
        for (int j = 0; j < CPL; j++) {
            ss = fmaf(hv[j], a_src[c0 + j], ss);
            sd = fmaf(hv[j], a_dst[c0 + j], sd);
        }
    }
#pragma unroll
    for (int o = G / 2; o > 0; o >>= 1) {
        ss += __shfl_down_sync(0xffffffffu, ss, o, G);
        sd += __shfl_down_sync(0xffffffffu, sd, o, G);
    }
    __shared__ float smax[4][H];
    if ((lane % G) == 0) {
        int hd = lane / G;
        if (valid) {
            g_als[(size_t)node * H + hd] = ss;
            g_ald[(size_t)node * H + hd] = sd;
        }
        smax[wid][hd] = valid ? ss : -1e30f;
    }
    __syncthreads();
    if (threadIdx.x < H) {
        float m = smax[0][threadIdx.x];
#pragma unroll
        for (int ww = 1; ww < 4; ww++) m = fmaxf(m, smax[ww][threadIdx.x]);
        atomicMax(&g_mxals[LAYER][threadIdx.x], fenc(m));
    }
}

// OUTH: write fp16 g_acth (layers 1-2) else fp32 outExt (layer 3).
template <int H, int C, bool RELU, int LAYER, bool OUTH>
__global__ void k_aggregate(const float* __restrict__ bias, float* __restrict__ outExt, int n) {
    constexpr int D = H * C;
    constexpr int CPL = D / 32;
    constexpr int G = 32 / H;
    int wid = threadIdx.x >> 5;
    int lane = threadIdx.x & 31;
    int node = blockIdx.x * 4 + wid;
    if (node >= n) return;

    int s0 = g_rowptr[node];
    int s1 = g_rowptr[node + 1];

    int c0 = lane * CPL;
    int hd = lane / G;
    float myald = g_ald[(size_t)node * H + hd];
    float Mh = fdec(g_mxals[LAYER][hd]);
    float mymx = Mh + myald;
    mymx = (mymx > 0.f) ? mymx : SLOPE * mymx;

    float acc[CPL];
#pragma unroll
    for (int j = 0; j < CPL; j++) acc[j] = 0.f;
    float esum = 0.f;

    int i = s0;
    for (; i + 4 <= s1; i += 4) {
        int2 p0 = g_csr[i + 0];
        int2 p1 = g_csr[i + 1];
        int2 p2 = g_csr[i + 2];
        int2 p3 = g_csr[i + 3];
        float a0 = g_als[(size_t)p0.x * H + hd];
        float a1 = g_als[(size_t)p1.x * H + hd];
        float a2 = g_als[(size_t)p2.x * H + hd];
        float a3 = g_als[(size_t)p3.x * H + hd];
        if (CPL == 4) {
            uint2 r0 = *(const uint2*)(g_h + (size_t)p0.x * D + c0);
            uint2 r1 = *(const uint2*)(g_h + (size_t)p1.x * D + c0);
            uint2 r2 = *(const uint2*)(g_h + (size_t)p2.x * D + c0);
            uint2 r3 = *(const uint2*)(g_h + (size_t)p3.x * D + c0);
            float l0 = a0 + myald; l0 = (l0 > 0.f) ? l0 : SLOPE * l0;
            float l1 = a1 + myald; l1 = (l1 > 0.f) ? l1 : SLOPE * l1;
            float l2 = a2 + myald; l2 = (l2 > 0.f) ? l2 : SLOPE * l2;
            float l3 = a3 + myald; l3 = (l3 > 0.f) ? l3 : SLOPE * l3;
            float e0 = __expf(l0 - mymx) * __int_as_float(p0.y);
            float e1 = __expf(l1 - mymx) * __int_as_float(p1.y);
            float e2 = __expf(l2 - mymx) * __int_as_float(p2.y);
            float e3 = __expf(l3 - mymx) * __int_as_float(p3.y);
            esum += (e0 + e1) + (e2 + e3);
            float2 f;
            f = __half22float2(*reinterpret_cast<__half2*>(&r0.x));
            acc[0] = fmaf(e0, f.x, acc[0]); acc[1] = fmaf(e0, f.y, acc[1]);
            f = __half22float2(*reinterpret_cast<__half2*>(&r0.y));
            acc[2] = fmaf(e0, f.x, acc[2]); acc[3] = fmaf(e0, f.y, acc[3]);
            f = __half22float2(*reinterpret_cast<__half2*>(&r1.x));
            acc[0] = fmaf(e1, f.x, acc[0]); acc[1] = fmaf(e1, f.y, acc[1]);
            f = __half22float2(*reinterpret_cast<__half2*>(&r1.y));
            acc[2] = fmaf(e1, f.x, acc[2]); acc[3] = fmaf(e1, f.y, acc[3]);
            f = __half22float2(*reinterpret_cast<__half2*>(&r2.x));
            acc[0] = fmaf(e2, f.x, acc[0]); acc[1] = fmaf(e2, f.y, acc[1]);
            f = __half22float2(*reinterpret_cast<__half2*>(&r2.y));
            acc[2] = fmaf(e2, f.x, acc[2]); acc[3] = fmaf(e2, f.y, acc[3]);
            f = __half22float2(*reinterpret_cast<__half2*>(&r3.x));
            acc[0] = fmaf(e3, f.x, acc[0]); acc[1] = fmaf(e3, f.y, acc[1]);
            f = __half22float2(*reinterpret_cast<__half2*>(&r3.y));
            acc[2] = fmaf(e3, f.x, acc[2]); acc[3] = fmaf(e3, f.y, acc[3]);
        } else {
            unsigned r0 = *(const unsigned*)(g_h + (size_t)p0.x * D + c0);
            unsigned r1 = *(const unsigned*)(g_h + (size_t)p1.x * D + c0);
            unsigned r2 = *(const unsigned*)(g_h + (size_t)p2.x * D + c0);
            unsigned r3 = *(const unsigned*)(g_h + (size_t)p3.x * D + c0);
            float l0 = a0 + myald; l0 = (l0 > 0.f) ? l0 : SLOPE * l0;
            float l1 = a1 + myald; l1 = (l1 > 0.f) ? l1 : SLOPE * l1;
            float l2 = a2 + myald; l2 = (l2 > 0.f) ? l2 : SLOPE * l2;
            float l3 = a3 + myald; l3 = (l3 > 0.f) ? l3 : SLOPE * l3;
            float e0 = __expf(l0 - mymx) * __int_as_float(p0.y);
            float e1 = __expf(l1 - mymx) * __int_as_float(p1.y);
            float e2 = __expf(l2 - mymx) * __int_as_float(p2.y);
            float e3 = __expf(l3 - mymx) * __int_as_float(p3.y);
            esum += (e0 + e1) + (e2 + e3);
            float2 f;
            f = __half22float2(*reinterpret_cast<__half2*>(&r0));
            acc[0] = fmaf(e0, f.x, acc[0]); acc[1] = fmaf(e0, f.y, acc[1]);
            f = __half22float2(*reinterpret_cast<__half2*>(&r1));
            acc[0] = fmaf(e1, f.x, acc[0]); acc[1] = fmaf(e1, f.y, acc[1]);
            f = __half22float2(*reinterpret_cast<__half2*>(&r2));
            acc[0] = fmaf(e2, f.x, acc[0]); acc[1] = fmaf(e2, f.y, acc[1]);
            f = __half22float2(*reinterpret_cast<__half2*>(&r3));
            acc[0] = fmaf(e3, f.x, acc[0]); acc[1] = fmaf(e3, f.y, acc[1]);
        }
    }
    for (; i < s1; i++) {
        int2 p = g_csr[i];
        float l = g_als[(size_t)p.x * H + hd] + myald;
        l = (l > 0.f) ? l : SLOPE * l;
        float e = __expf(l - mymx) * __int_as_float(p.y);
        esum += e;
        const __half* hp = g_h + (size_t)p.x * D + c0;
        if (CPL == 4) {
            uint2 raw = *(const uint2*)hp;
            float2 f01 = __half22float2(*reinterpret_cast<__half2*>(&raw.x));
            float2 f23 = __half22float2(*reinterpret_cast<__half2*>(&raw.y));
            acc[0] = fmaf(e, f01.x, acc[0]);
            acc[1] = fmaf(e, f01.y, acc[1]);
            acc[2] = fmaf(e, f23.x, acc[2]);
            acc[3] = fmaf(e, f23.y, acc[3]);
        } else {
            unsigned raw = *(const unsigned*)hp;
            float2 f01 = __half22float2(*reinterpret_cast<__half2*>(&raw));
            acc[0] = fmaf(e, f01.x, acc[0]);
            acc[1] = fmaf(e, f01.y, acc[1]);
        }
    }
    float inv = 1.0f / (esum + 1e-16f);
    float vout[CPL];
#pragma unroll
    for (int j = 0; j < CPL; j++) {
        float v = fmaf(acc[j], inv, bias[c0 + j]);
        if (RELU) v = fmaxf(v, 0.f);
        vout[j] = v;
    }
    if (OUTH) {
        __half* op = g_acth + (size_t)node * D + c0;
        __half2 h01 = __floats2half2_rn(vout[0], vout[1]);
        if (CPL == 4) {
            __half2 h23 = __floats2half2_rn(vout[2], vout[3]);
            *reinterpret_cast<uint2*>(op) =
                make_uint2(*reinterpret_cast<unsigned*>(&h01),
                           *reinterpret_cast<unsigned*>(&h23));
        } else {
            *reinterpret_cast<unsigned*>(op) = *reinterpret_cast<unsigned*>(&h01);
        }
    } else {
#pragma unroll
        for (int j = 0; j < CPL; j++)
            outExt[(size_t)node * D + c0 + j] = vout[j];
    }
}

// ---------------- host launch ----------------
extern "C" void kernel_launch(void* const* d_in, const int* in_sizes, int n_in,
                              void* d_out, int out_size) {
    const float* x   = (const float*)d_in[0];
    const void*  ei  = d_in[1];
    const float* ew  = (const float*)d_in[2];
    const float* W1  = (const float*)d_in[3];
    const float* aS1 = (const float*)d_in[4];
    const float* aD1 = (const float*)d_in[5];
    const float* b1  = (const float*)d_in[6];
    const float* W2  = (const float*)d_in[7];
    const float* aS2 = (const float*)d_in[8];
    const float* aD2 = (const float*)d_in[9];
    const float* b2  = (const float*)d_in[10];
    const float* W3  = (const float*)d_in[11];
    const float* aS3 = (const float*)d_in[12];
    const float* aD3 = (const float*)d_in[13];
    const float* b3  = (const float*)d_in[14];

    const int E = in_sizes[2];
    const int n = NN;

    static cudaStream_t s1 = nullptr;
    static cudaEvent_t evFork = nullptr, evJoin = nullptr;
    if (!s1) {
        cudaStreamCreateWithFlags(&s1, cudaStreamNonBlocking);
        cudaEventCreateWithFlags(&evFork, cudaEventDisableTiming);
        cudaEventCreateWithFlags(&evJoin, cudaEventDisableTiming);
    }
    cudaStream_t s0 = 0;

    const int nodeBlocks = (n + 3) / 4;
    dim3 gemmGrid2(D1 / 64, (n + 127) / 128);
    dim3 gemmGrid1(OUT_F / 64, (n + 127) / 128);

    // Fork: x->fp16 convert + layer-1 GEMM on s1, concurrent with CSR on s0.
    cudaEventRecord(evFork, s0);
    cudaStreamWaitEvent(s1, evFork, 0);
    int total8 = n * IN_F / 8;
    k_x2h<<<(total8 + 255) / 256, 256, 0, s1>>>(x, total8);
    k_gemm_f16<0><<<gemmGrid2, 256, 0, s1>>>(W1, n, IN_F, D1);

    k_detect_zero<<<(n + 255) / 256, 256, 0, s0>>>(ei, E, n);
    k_count_deg<<<(E + 255) / 256, 256, 0, s0>>>(ei, E, n);
    k_scan1<<<NBLK, SCAN_B, 0, s0>>>(n);
    k_scan2<<<1, 64, 0, s0>>>();
    k_scan3<<<(n + 255) / 256, 256, 0, s0>>>(n);
    k_scatter<<<(E + 255) / 256, 256, 0, s0>>>(ei, ew, E, n);

    cudaEventRecord(evJoin, s1);
    cudaStreamWaitEvent(s0, evJoin, 0);

    // Layer 1: 256 -> 128, H=4, C=32, relu -> fp16 act
    k_dots<4, 32, 0><<<nodeBlocks, 128, 0, s0>>>(aS1, aD1, n);
    k_aggregate<4, 32, true, 0, true><<<nodeBlocks, 128, 0, s0>>>(b1, nullptr, n);

    // Layer 2: 128 -> 128, H=4, C=32, relu -> fp16 act
    k_gemm_f16<1><<<gemmGrid2, 256, 0, s0>>>(W2, n, D1, D1);
    k_dots<4, 32, 1><<<nodeBlocks, 128, 0, s0>>>(aS2, aD2, n);
    k_aggregate<4, 32, true, 1, true><<<nodeBlocks, 128, 0, s0>>>(b2, nullptr, n);

    // Layer 3: 128 -> 64, H=1, C=64, no relu -> fp32 d_out
    k_gemm_f16<1><<<gemmGrid1, 256, 0, s0>>>(W3, n, D1, OUT_F);
    k_dots<1, 64, 2><<<nodeBlocks, 128, 0, s0>>>(aS3, aD3, n);
    k_aggregate<1, 64, false, 2, false><<<nodeBlocks, 128, 0, s0>>>(b3, (float*)d_out, n);
}